// round 4
// baseline (speedup 1.0000x reference)
#include <cuda_runtime.h>
#include <math.h>

#define NN 1024
#define DD 512
#define HH 16
#define DH 32
#define NBINS 68

// ---- scratch layout (float offsets into one big __device__ buffer) ----
#define OFF_HN     0
#define OFF_Q      524288
#define OFF_K      1048576
#define OFF_V      1572864
#define OFF_G      2097152
#define OFF_LOGK   2621440
#define OFF_LOGMU  19398656
#define OFF_LOGNU  19415040
#define OFF_U      19431424
#define OFF_V2     19447808
#define OFF_VXP    19464192
#define OFF_ATTN   20037632
#define OFF_XC     20561920
#define OFF_HMID   20611072
#define OFF_H2     21135360
#define OFF_FFA    21659648
#define OFF_FFB    23756800
#define OFF_FFG    25853952
#define BUF_TOTAL  27951104

__device__ float g_buf[BUF_TOTAL];

// Output layout: [h | x_res | log_u | log_v]
#define OUT_H 0
#define OUT_X 524288
#define OUT_U 527360
#define OUT_V 543744

// ---------------------------------------------------------------------------
// LayerNorm over last dim D=512. One block per row, 256 threads.
__global__ void ln_kernel(const float* __restrict__ inExt, int inOff,
                          const float* __restrict__ w, const float* __restrict__ b,
                          int outOff) {
    const float* in = inExt ? inExt : (g_buf + inOff);
    int row = blockIdx.x, tid = threadIdx.x;
    __shared__ float red[256];
    float x0 = in[row * DD + tid];
    float x1 = in[row * DD + 256 + tid];
    red[tid] = x0 + x1;
    __syncthreads();
    for (int o = 128; o; o >>= 1) { if (tid < o) red[tid] += red[tid + o]; __syncthreads(); }
    float m = red[0] * (1.0f / DD);
    __syncthreads();
    float d0 = x0 - m, d1 = x1 - m;
    red[tid] = d0 * d0 + d1 * d1;
    __syncthreads();
    for (int o = 128; o; o >>= 1) { if (tid < o) red[tid] += red[tid + o]; __syncthreads(); }
    float var = red[0] * (1.0f / DD);
    float rs = rsqrtf(var + 1e-5f);
    float* out = g_buf + outOff;
    out[row * DD + tid]       = d0 * rs * w[tid]       + b[tid];
    out[row * DD + 256 + tid] = d1 * rs * w[tid + 256] + b[tid + 256];
}

// ---------------------------------------------------------------------------
// SGEMM: C[M,N] = A[M,K] @ B[N,K]^T  (+ optional residual/mask epilogue)
// A = scratch(aOff). out = outExt ? outExt : g_buf+cOff.
// res = resExt ? resExt : (resOff>=0 ? g_buf+resOff : none). out = res + C*mask[row].
__global__ void sgemm_kernel(int aOff, const float* __restrict__ B, int cOff,
                             float* __restrict__ outExt,
                             const float* __restrict__ resExt, int resOff,
                             const float* __restrict__ mask,
                             int M, int N, int K) {
    __shared__ float As[16 * 65];
    __shared__ float Bs[16 * 65];
    const float* A = g_buf + aOff;
    float* outp = outExt ? outExt : (g_buf + cOff);
    const float* resp = resExt ? resExt : (resOff >= 0 ? (g_buf + resOff) : (const float*)0);

    int tid = threadIdx.x;
    int tx = tid & 15, ty = tid >> 4;
    int m0 = blockIdx.y * 64, n0 = blockIdx.x * 64;

    float acc[4][4];
#pragma unroll
    for (int i = 0; i < 4; ++i)
#pragma unroll
        for (int j = 0; j < 4; ++j) acc[i][j] = 0.0f;

    for (int k0 = 0; k0 < K; k0 += 16) {
        for (int t = tid; t < 64 * 16; t += 256) {
            int r = t >> 4, kk = t & 15;
            As[kk * 65 + r] = A[(m0 + r) * K + k0 + kk];
            Bs[kk * 65 + r] = B[(n0 + r) * K + k0 + kk];
        }
        __syncthreads();
#pragma unroll
        for (int kk = 0; kk < 16; ++kk) {
            float a[4], bb[4];
#pragma unroll
            for (int i = 0; i < 4; ++i) a[i] = As[kk * 65 + ty + 16 * i];
#pragma unroll
            for (int j = 0; j < 4; ++j) bb[j] = Bs[kk * 65 + tx + 16 * j];
#pragma unroll
            for (int i = 0; i < 4; ++i)
#pragma unroll
                for (int j = 0; j < 4; ++j) acc[i][j] += a[i] * bb[j];
        }
        __syncthreads();
    }
#pragma unroll
    for (int i = 0; i < 4; ++i) {
        int row = m0 + ty + 16 * i;
        float mk = mask ? mask[row] : 1.0f;
#pragma unroll
        for (int j = 0; j < 4; ++j) {
            int col = n0 + tx + 16 * j;
            float v = acc[i][j];
            if (resp) v = resp[row * N + col] + v * mk;
            outp[row * N + col] = v;
        }
    }
}

// ---------------------------------------------------------------------------
// Per-head plain LN over DH=32 (one warp per (token,head) vector), in place.
__global__ void headln_kernel(int off) {
    int gid = blockIdx.x * 8 + (threadIdx.x >> 5);
    int lane = threadIdx.x & 31;
    int i = gid >> 4, h = gid & 15;
    float* p = g_buf + off + i * DD + h * DH + lane;
    float x = *p;
    float s = x;
#pragma unroll
    for (int o = 16; o; o >>= 1) s += __shfl_xor_sync(0xffffffffu, s, o);
    float m = s * (1.0f / DH);
    float d = x - m;
    float v = d * d;
#pragma unroll
    for (int o = 16; o; o >>= 1) v += __shfl_xor_sync(0xffffffffu, v, o);
    float var = v * (1.0f / DH);
    *p = d * rsqrtf(var + 1e-5f);
}

// ---------------------------------------------------------------------------
// logK[h,i,j] = pair_mask ? (QK/sqrt(32) + bias - sigmoid(wdl)*d2/100)/eps_h : -1e9
__global__ void logk_kernel(const int* __restrict__ bins, const float* __restrict__ pw,
                            const float* __restrict__ wdl, const float* __restrict__ eps,
                            const float* __restrict__ mask, const float* __restrict__ xr) {
    __shared__ float Qs[32 * 65], Ks[32 * 65];
    __shared__ float xi[64][3], xj[64][3], mi[64], mj[64], pwh[NBINS];
    int h = blockIdx.z, i0 = blockIdx.y * 64, j0 = blockIdx.x * 64;
    int tid = threadIdx.x;
    for (int t = tid; t < 64 * 32; t += 256) {
        int r = t >> 5, k = t & 31;
        Qs[k * 65 + r] = g_buf[OFF_Q + (i0 + r) * DD + h * DH + k];
        Ks[k * 65 + r] = g_buf[OFF_K + (j0 + r) * DD + h * DH + k];
    }
    if (tid < 64) {
        mi[tid] = mask[i0 + tid];
        mj[tid] = mask[j0 + tid];
        xi[tid][0] = xr[(i0 + tid) * 3 + 0];
        xi[tid][1] = xr[(i0 + tid) * 3 + 1];
        xi[tid][2] = xr[(i0 + tid) * 3 + 2];
        xj[tid][0] = xr[(j0 + tid) * 3 + 0];
        xj[tid][1] = xr[(j0 + tid) * 3 + 1];
        xj[tid][2] = xr[(j0 + tid) * 3 + 2];
    }
    if (tid < NBINS) pwh[tid] = pw[tid * HH + h];
    __syncthreads();

    int tx = tid & 15, ty = tid >> 4;
    float acc[4][4];
#pragma unroll
    for (int i = 0; i < 4; ++i)
#pragma unroll
        for (int j = 0; j < 4; ++j) acc[i][j] = 0.0f;
#pragma unroll
    for (int k = 0; k < 32; ++k) {
        float a[4], b[4];
#pragma unroll
        for (int i = 0; i < 4; ++i) a[i] = Qs[k * 65 + ty + 16 * i];
#pragma unroll
        for (int j = 0; j < 4; ++j) b[j] = Ks[k * 65 + tx + 16 * j];
#pragma unroll
        for (int i = 0; i < 4; ++i)
#pragma unroll
            for (int j = 0; j < 4; ++j) acc[i][j] += a[i] * b[j];
    }
    float wd = 1.0f / (1.0f + expf(-wdl[h]));
    float ie = 1.0f / eps[h];
    const float s32 = 0.17677669529663687f;  // 1/sqrt(32)
#pragma unroll
    for (int ii = 0; ii < 4; ++ii) {
        int il = ty + 16 * ii, i = i0 + il;
#pragma unroll
        for (int jj = 0; jj < 4; ++jj) {
            int jl = tx + 16 * jj, j = j0 + jl;
            int bn = bins[i * NN + j];
            float d0 = xi[il][0] - xj[jl][0];
            float d1 = xi[il][1] - xj[jl][1];
            float d2c = xi[il][2] - xj[jl][2];
            float dd = d0 * d0 + d1 * d1 + d2c * d2c;
            float logit = acc[ii][jj] * s32 + pwh[bn] - wd * dd * 0.01f;
            float lk = (mi[il] * mj[jl] > 0.0f) ? logit * ie : -1e9f;
            g_buf[OFF_LOGK + (h * NN + i) * NN + j] = lk;
        }
    }
}

// ---------------------------------------------------------------------------
__global__ void skprep_kernel(const float* __restrict__ mu, const float* __restrict__ nu,
                              const float* __restrict__ lup, const float* __restrict__ lvp) {
    int idx = blockIdx.x * 256 + threadIdx.x;
    if (idx >= HH * NN) return;
    g_buf[OFF_LOGMU + idx] = logf(fmaxf(mu[idx], 1e-8f));
    g_buf[OFF_LOGNU + idx] = logf(fmaxf(nu[idx], 1e-8f));
    g_buf[OFF_U + idx] = lup[idx];
    g_buf[OFF_V2 + idx] = lvp[idx];
}

// log_u[h,i] = fi*(log_mu - LSE_j(logK[h,i,j] + log_v[h,j]))
__global__ void sk_u_kernel(const float* __restrict__ eps) {
    __shared__ float sv[NN];
    int h = blockIdx.y;
    for (int t = threadIdx.x; t < NN; t += 256) sv[t] = g_buf[OFF_V2 + h * NN + t];
    __syncthreads();
    int w = threadIdx.x >> 5, lane = threadIdx.x & 31;
    int i = blockIdx.x * 8 + w;
    const float* row = g_buf + OFF_LOGK + (h * NN + i) * NN;
    float m = -INFINITY, s = 0.0f;
#pragma unroll 4
    for (int j = lane; j < NN; j += 32) {
        float x = row[j] + sv[j];
        if (x > m) { s *= __expf(m - x); m = x; }
        s += __expf(x - m);
    }
#pragma unroll
    for (int o = 16; o; o >>= 1) {
        float mo = __shfl_xor_sync(0xffffffffu, m, o);
        float so = __shfl_xor_sync(0xffffffffu, s, o);
        float nm = fmaxf(m, mo);
        s = s * __expf(m - nm) + so * __expf(mo - nm);
        m = nm;
    }
    if (lane == 0) {
        float fi = 1.0f / (1.0f + eps[h]);
        g_buf[OFF_U + h * NN + i] = fi * (g_buf[OFF_LOGMU + h * NN + i] - (m + logf(s)));
    }
}

// log_v[h,j] = fi*(log_nu - LSE_i(logK[h,i,j] + log_u[h,i]))
__global__ void sk_v_kernel(const float* __restrict__ eps) {
    __shared__ float su[NN];
    __shared__ float rm[8][33], rsum[8][33];
    int h = blockIdx.y;
    for (int t = threadIdx.x; t < NN; t += 256) su[t] = g_buf[OFF_U + h * NN + t];
    __syncthreads();
    int jx = threadIdx.x & 31, sy = threadIdx.x >> 5;
    int j = blockIdx.x * 32 + jx;
    const float* col = g_buf + OFF_LOGK + h * NN * NN + j;
    float m = -INFINITY, s = 0.0f;
    int i0 = sy * 128;
#pragma unroll 4
    for (int t = 0; t < 128; ++t) {
        int i = i0 + t;
        float x = col[i * NN] + su[i];
        if (x > m) { s *= __expf(m - x); m = x; }
        s += __expf(x - m);
    }
    rm[sy][jx] = m; rsum[sy][jx] = s;
    __syncthreads();
    if (sy == 0) {
        float M = m, S = s;
#pragma unroll
        for (int k = 1; k < 8; ++k) {
            float mo = rm[k][jx], so = rsum[k][jx];
            float nm = fmaxf(M, mo);
            S = S * __expf(M - nm) + so * __expf(mo - nm);
            M = nm;
        }
        float fi = 1.0f / (1.0f + eps[h]);
        g_buf[OFF_V2 + h * NN + j] = fi * (g_buf[OFF_LOGNU + h * NN + j] - (M + logf(S)));
    }
}

// ---------------------------------------------------------------------------
// Pack Vx[h][j][c]: c<32 -> V head slice, c=32..34 -> x_res
__global__ void pack_kernel(const float* __restrict__ xr) {
    int idx = blockIdx.x * 256 + threadIdx.x;
    if (idx >= HH * NN * 35) return;
    int c = idx % 35;
    int hj = idx / 35;
    int j = hj & (NN - 1);
    int h = hj >> 10;
    float v = (c < 32) ? g_buf[OFF_V + j * DD + h * DH + c] : xr[j * 3 + (c - 32)];
    g_buf[OFF_VXP + idx] = v;
}

// Fused: P=exp(logK+u+v), rowsum clip, attn = Pn@V * sigmoid(G), x_cent = Pn@x_res.
// 512 blocks = 16 heads x 32 row-blocks of 32 rows. Warp handles 4 rows.
__global__ void __launch_bounds__(256, 1) attn_kernel() {
    __shared__ float sVx[256 * 35];
    __shared__ float sv[256];
    int h = blockIdx.x >> 5;
    int w = threadIdx.x >> 5, lane = threadIdx.x & 31;
    int i0 = (blockIdx.x & 31) * 32 + w * 4;
    float uu0 = g_buf[OFF_U + h * NN + i0 + 0];
    float uu1 = g_buf[OFF_U + h * NN + i0 + 1];
    float uu2 = g_buf[OFF_U + h * NN + i0 + 2];
    float uu3 = g_buf[OFF_U + h * NN + i0 + 3];
    const float* lk0 = g_buf + OFF_LOGK + (h * NN + i0) * NN;

    float acc[4][35];
#pragma unroll
    for (int r = 0; r < 4; ++r)
#pragma unroll
        for (int c = 0; c < 35; ++c) acc[r][c] = 0.0f;
    float rs0 = 0.f, rs1 = 0.f, rs2 = 0.f, rs3 = 0.f;

    for (int cb = 0; cb < 4; ++cb) {
        int jb = cb * 256;
        __syncthreads();
        const float* src = g_buf + OFF_VXP + (h * NN + jb) * 35;
        for (int t = threadIdx.x; t < 256 * 35; t += 256) sVx[t] = src[t];
        sv[threadIdx.x] = g_buf[OFF_V2 + h * NN + jb + threadIdx.x];
        __syncthreads();
#pragma unroll 1
        for (int s = 0; s < 8; ++s) {
            int jl = s * 32 + lane;
            int j = jb + jl;
            float vj = sv[jl];
            float p0 = __expf(lk0[0 * NN + j] + uu0 + vj);
            float p1 = __expf(lk0[1 * NN + j] + uu1 + vj);
            float p2 = __expf(lk0[2 * NN + j] + uu2 + vj);
            float p3 = __expf(lk0[3 * NN + j] + uu3 + vj);
            rs0 += p0; rs1 += p1; rs2 += p2; rs3 += p3;
            const float* vp = sVx + jl * 35;
#pragma unroll
            for (int c = 0; c < 35; ++c) {
                float vv = vp[c];
                acc[0][c] += p0 * vv;
                acc[1][c] += p1 * vv;
                acc[2][c] += p2 * vv;
                acc[3][c] += p3 * vv;
            }
        }
    }

    float rsv[4] = {rs0, rs1, rs2, rs3};
#pragma unroll
    for (int r = 0; r < 4; ++r) {
        float t = rsv[r];
#pragma unroll
        for (int o = 16; o; o >>= 1) t += __shfl_xor_sync(0xffffffffu, t, o);
        rsv[r] = fmaxf(t, 1e-8f);
    }
#pragma unroll
    for (int r = 0; r < 4; ++r) {
        int i = i0 + r;
        float inv = 1.0f / rsv[r];
#pragma unroll
        for (int c = 0; c < 35; ++c) {
            float a = acc[r][c];
#pragma unroll
            for (int o = 16; o; o >>= 1) a += __shfl_xor_sync(0xffffffffu, a, o);
            if (c < 32) {
                if (lane == c) {
                    float g = g_buf[OFF_G + i * DD + h * DH + c];
                    float sg = 1.0f / (1.0f + __expf(-g));
                    g_buf[OFF_ATTN + i * DD + h * DH + c] = a * inv * sg;
                }
            } else {
                if (lane == c - 32) {
                    g_buf[OFF_XC + (h * NN + i) * 3 + (c - 32)] = a * inv;
                }
            }
        }
    }
}

// ---------------------------------------------------------------------------
__global__ void xupd_kernel(const float* __restrict__ xr, const float* __restrict__ mask,
                            const float* __restrict__ gamma, float* __restrict__ out) {
    int i = blockIdx.x * 256 + threadIdx.x;
    if (i >= NN) return;
    float x0 = xr[i * 3 + 0], x1 = xr[i * 3 + 1], x2 = xr[i * 3 + 2];
    float a0 = 0.f, a1 = 0.f, a2 = 0.f;
#pragma unroll
    for (int h = 0; h < HH; ++h) {
        float th = tanhf(gamma[h]) * (1.0f / HH);
        const float* xc = g_buf + OFF_XC + (h * NN + i) * 3;
        a0 += th * (x0 - xc[0]);
        a1 += th * (x1 - xc[1]);
        a2 += th * (x2 - xc[2]);
    }
    float mk = mask[i];
    out[i * 3 + 0] = x0 + a0 * mk;
    out[i * 3 + 1] = x1 + a1 * mk;
    out[i * 3 + 2] = x2 + a2 * mk;
}

__global__ void copyuv_kernel(float* __restrict__ out) {
    int idx = blockIdx.x * 256 + threadIdx.x;
    if (idx >= HH * NN) return;
    out[OUT_U + idx] = g_buf[OFF_U + idx];
    out[OUT_V + idx] = g_buf[OFF_V2 + idx];
}

__global__ void silu_kernel() {
    int idx = blockIdx.x * 256 + threadIdx.x;
    if (idx >= NN * 4 * DD) return;
    float a = g_buf[OFF_FFA + idx];
    float b = g_buf[OFF_FFB + idx];
    g_buf[OFF_FFG + idx] = a * b / (1.0f + __expf(-a));
}

// ---------------------------------------------------------------------------
extern "C" void kernel_launch(void* const* d_in, const int* in_sizes, int n_in,
                              void* d_out, int out_size) {
    const float* h    = (const float*)d_in[0];
    const float* xres = (const float*)d_in[1];
    const float* mu   = (const float*)d_in[2];
    const float* nu   = (const float*)d_in[3];
    const float* lup  = (const float*)d_in[4];
    const float* lvp  = (const float*)d_in[5];
    const float* mask = (const float*)d_in[6];
    const float* lnw  = (const float*)d_in[7];
    const float* lnb  = (const float*)d_in[8];
    const float* wq   = (const float*)d_in[9];
    const float* wk   = (const float*)d_in[10];
    const float* wv   = (const float*)d_in[11];
    const float* wg   = (const float*)d_in[12];
    const float* wo   = (const float*)d_in[13];
    const float* gamma= (const float*)d_in[14];
    const float* pw   = (const float*)d_in[15];
    const float* wdl  = (const float*)d_in[16];
    const float* lnfw = (const float*)d_in[17];
    const float* lnfb = (const float*)d_in[18];
    const float* w1   = (const float*)d_in[19];
    const float* w3   = (const float*)d_in[20];
    const float* w2   = (const float*)d_in[21];
    const int*   bins = (const int*)d_in[22];
    const float* eps  = (const float*)d_in[23];
    float* out = (float*)d_out;

    // 1. pre-LN
    ln_kernel<<<NN, 256>>>(h, 0, lnw, lnb, OFF_HN);

    // 2. Q/K/V/G projections
    dim3 g512(DD / 64, NN / 64);
    sgemm_kernel<<<g512, 256>>>(OFF_HN, wq, OFF_Q, 0, 0, -1, 0, NN, DD, DD);
    sgemm_kernel<<<g512, 256>>>(OFF_HN, wk, OFF_K, 0, 0, -1, 0, NN, DD, DD);
    sgemm_kernel<<<g512, 256>>>(OFF_HN, wv, OFF_V, 0, 0, -1, 0, NN, DD, DD);
    sgemm_kernel<<<g512, 256>>>(OFF_HN, wg, OFF_G, 0, 0, -1, 0, NN, DD, DD);

    // 3. per-head plain LN on Q, K
    headln_kernel<<<2048, 256>>>(OFF_Q);
    headln_kernel<<<2048, 256>>>(OFF_K);

    // 4. logK
    logk_kernel<<<dim3(16, 16, 16), 256>>>(bins, pw, wdl, eps, mask, xres);

    // 5. Sinkhorn
    skprep_kernel<<<64, 256>>>(mu, nu, lup, lvp);
    for (int it = 0; it < 20; ++it) {
        sk_u_kernel<<<dim3(128, 16), 256>>>(eps);
        sk_v_kernel<<<dim3(32, 16), 256>>>(eps);
    }
    copyuv_kernel<<<64, 256>>>(out);

    // 6. fused transport-plan attention + centroids
    pack_kernel<<<(HH * NN * 35 + 255) / 256, 256>>>(xres);
    attn_kernel<<<512, 256>>>();
    xupd_kernel<<<4, 256>>>(xres, mask, gamma, out + OUT_X);

    // 7. output projection + residual
    sgemm_kernel<<<g512, 256>>>(OFF_ATTN, wo, OFF_HMID, 0, h, -1, mask, NN, DD, DD);

    // 8. FFN
    ln_kernel<<<NN, 256>>>(0, OFF_HMID, lnfw, lnfb, OFF_H2);
    dim3 g2048(4 * DD / 64, NN / 64);
    sgemm_kernel<<<g2048, 256>>>(OFF_H2, w1, OFF_FFA, 0, 0, -1, 0, NN, 4 * DD, DD);
    sgemm_kernel<<<g2048, 256>>>(OFF_H2, w3, OFF_FFB, 0, 0, -1, 0, NN, 4 * DD, DD);
    silu_kernel<<<(NN * 4 * DD + 255) / 256, 256>>>();
    sgemm_kernel<<<g512, 256>>>(OFF_FFG, w2, 0, out + OUT_H, 0, OFF_HMID, mask, NN, DD, 4 * DD);
}

// round 5
// speedup vs baseline: 1.5141x; 1.5141x over previous
#include <cuda_runtime.h>
#include <math.h>

#define NN 1024
#define DD 512
#define HH 16
#define DH 32
#define NBINS 68

// ---- scratch layout (float offsets into one big __device__ buffer) ----
#define OFF_HN     0
#define OFF_Q      524288
#define OFF_K      1048576
#define OFF_V      1572864
#define OFF_G      2097152
#define OFF_LOGK   2621440
#define OFF_LOGMU  19398656
#define OFF_LOGNU  19415040
#define OFF_U      19431424
#define OFF_V2     19447808
#define OFF_VXP    19464192
#define OFF_ATTN   20037632
#define OFF_XC     20561920
#define OFF_HMID   20611072
#define OFF_H2     21135360
#define OFF_FFA    21659648
#define OFF_FFB    23756800
#define OFF_FFG    25853952
#define BUF_TOTAL  27951104

__device__ float g_buf[BUF_TOTAL];

// Output layout: [h | x_res | log_u | log_v]
#define OUT_H 0
#define OUT_X 524288
#define OUT_U 527360
#define OUT_V 543744

// ---------------------------------------------------------------------------
// LayerNorm over last dim D=512. One block per row, 256 threads.
__global__ void ln_kernel(const float* __restrict__ inExt, int inOff,
                          const float* __restrict__ w, const float* __restrict__ b,
                          int outOff) {
    const float* in = inExt ? inExt : (g_buf + inOff);
    int row = blockIdx.x, tid = threadIdx.x;
    __shared__ float red[256];
    float x0 = in[row * DD + tid];
    float x1 = in[row * DD + 256 + tid];
    red[tid] = x0 + x1;
    __syncthreads();
    for (int o = 128; o; o >>= 1) { if (tid < o) red[tid] += red[tid + o]; __syncthreads(); }
    float m = red[0] * (1.0f / DD);
    __syncthreads();
    float d0 = x0 - m, d1 = x1 - m;
    red[tid] = d0 * d0 + d1 * d1;
    __syncthreads();
    for (int o = 128; o; o >>= 1) { if (tid < o) red[tid] += red[tid + o]; __syncthreads(); }
    float var = red[0] * (1.0f / DD);
    float rs = rsqrtf(var + 1e-5f);
    float* out = g_buf + outOff;
    out[row * DD + tid]       = d0 * rs * w[tid]       + b[tid];
    out[row * DD + 256 + tid] = d1 * rs * w[tid + 256] + b[tid + 256];
}

// ---------------------------------------------------------------------------
// GEMM: C[M, n] = A[M,K] @ B[n,K]^T, with up to 4 weight matrices laid out as
// consecutive nPerW-wide output segments (each segment [M][nPerW], row stride
// nPerW). Optional epilogue: out = res + C*mask[row].
// Tile BM x 64, 256 threads, each thread computes (BM/16) x 4.
template<int BM>
__global__ void __launch_bounds__(256) gemm_kernel(
    int aOff, const float* __restrict__ B0, const float* __restrict__ B1,
    const float* __restrict__ B2, const float* __restrict__ B3,
    int nPerW, int cOff, float* __restrict__ outExt,
    const float* __restrict__ resExt, int resOff,
    const float* __restrict__ mask, int M, int K) {
    constexpr int TM = BM / 16;
    __shared__ float As[16][BM + 4];
    __shared__ float Bs[16][68];
    const float* A = g_buf + aOff;
    int m0 = blockIdx.y * BM, n0 = blockIdx.x * 64;
    int widx = n0 / nPerW;
    const float* Bw = (widx == 0) ? B0 : (widx == 1) ? B1 : (widx == 2) ? B2 : B3;
    int nloc0 = n0 - widx * nPerW;

    int tid = threadIdx.x;
    int tx = tid & 15, ty = tid >> 4;

    float acc[TM][4];
#pragma unroll
    for (int i = 0; i < TM; ++i)
#pragma unroll
        for (int j = 0; j < 4; ++j) acc[i][j] = 0.0f;

    int rB = tid >> 2, kqB = (tid & 3) << 2;

    for (int k0 = 0; k0 < K; k0 += 16) {
#pragma unroll
        for (int t0 = 0; t0 < BM * 4; t0 += 256) {
            int t = t0 + tid;
            int r = t >> 2, kq = (t & 3) << 2;
            float4 v = *(const float4*)&A[(m0 + r) * K + k0 + kq];
            As[kq + 0][r] = v.x; As[kq + 1][r] = v.y;
            As[kq + 2][r] = v.z; As[kq + 3][r] = v.w;
        }
        {
            float4 v = *(const float4*)&Bw[(nloc0 + rB) * K + k0 + kqB];
            Bs[kqB + 0][rB] = v.x; Bs[kqB + 1][rB] = v.y;
            Bs[kqB + 2][rB] = v.z; Bs[kqB + 3][rB] = v.w;
        }
        __syncthreads();
#pragma unroll
        for (int kk = 0; kk < 16; ++kk) {
            float4 b = *(const float4*)&Bs[kk][tx * 4];
#pragma unroll
            for (int ii = 0; ii < TM; ii += 4) {
                float4 a = *(const float4*)&As[kk][ty * TM + ii];
                acc[ii + 0][0] += a.x * b.x; acc[ii + 0][1] += a.x * b.y;
                acc[ii + 0][2] += a.x * b.z; acc[ii + 0][3] += a.x * b.w;
                acc[ii + 1][0] += a.y * b.x; acc[ii + 1][1] += a.y * b.y;
                acc[ii + 1][2] += a.y * b.z; acc[ii + 1][3] += a.y * b.w;
                acc[ii + 2][0] += a.z * b.x; acc[ii + 2][1] += a.z * b.y;
                acc[ii + 2][2] += a.z * b.z; acc[ii + 2][3] += a.z * b.w;
                acc[ii + 3][0] += a.w * b.x; acc[ii + 3][1] += a.w * b.y;
                acc[ii + 3][2] += a.w * b.z; acc[ii + 3][3] += a.w * b.w;
            }
        }
        __syncthreads();
    }

    float* outp = (outExt ? outExt : (g_buf + cOff)) + widx * M * nPerW;
    const float* resp = resExt ? resExt : (resOff >= 0 ? (g_buf + resOff) : (const float*)0);
    int col = nloc0 + tx * 4;
#pragma unroll
    for (int i = 0; i < TM; ++i) {
        int row = m0 + ty * TM + i;
        float4 v = make_float4(acc[i][0], acc[i][1], acc[i][2], acc[i][3]);
        if (resp) {
            float mk = mask ? mask[row] : 1.0f;
            float4 r4 = *(const float4*)&resp[row * nPerW + col];
            v.x = r4.x + v.x * mk; v.y = r4.y + v.y * mk;
            v.z = r4.z + v.z * mk; v.w = r4.w + v.w * mk;
        }
        *(float4*)&outp[row * nPerW + col] = v;
    }
}

// ---------------------------------------------------------------------------
// Per-head plain LN over DH=32 (one warp per (token,head) vector), in place.
__global__ void headln_kernel(int off) {
    int gid = blockIdx.x * 8 + (threadIdx.x >> 5);
    int lane = threadIdx.x & 31;
    int i = gid >> 4, h = gid & 15;
    float* p = g_buf + off + i * DD + h * DH + lane;
    float x = *p;
    float s = x;
#pragma unroll
    for (int o = 16; o; o >>= 1) s += __shfl_xor_sync(0xffffffffu, s, o);
    float m = s * (1.0f / DH);
    float d = x - m;
    float v = d * d;
#pragma unroll
    for (int o = 16; o; o >>= 1) v += __shfl_xor_sync(0xffffffffu, v, o);
    float var = v * (1.0f / DH);
    *p = d * rsqrtf(var + 1e-5f);
}

// ---------------------------------------------------------------------------
// logK[h,i,j] = pair_mask ? (QK/sqrt(32) + bias - sigmoid(wdl)*d2/100)/eps_h : -1e9
__global__ void logk_kernel(const int* __restrict__ bins, const float* __restrict__ pw,
                            const float* __restrict__ wdl, const float* __restrict__ eps,
                            const float* __restrict__ mask, const float* __restrict__ xr) {
    __shared__ float Qs[32 * 65], Ks[32 * 65];
    __shared__ float xi[64][3], xj[64][3], mi[64], mj[64], pwh[NBINS];
    int h = blockIdx.z, i0 = blockIdx.y * 64, j0 = blockIdx.x * 64;
    int tid = threadIdx.x;
    for (int t = tid; t < 64 * 32; t += 256) {
        int r = t >> 5, k = t & 31;
        Qs[k * 65 + r] = g_buf[OFF_Q + (i0 + r) * DD + h * DH + k];
        Ks[k * 65 + r] = g_buf[OFF_K + (j0 + r) * DD + h * DH + k];
    }
    if (tid < 64) {
        mi[tid] = mask[i0 + tid];
        mj[tid] = mask[j0 + tid];
        xi[tid][0] = xr[(i0 + tid) * 3 + 0];
        xi[tid][1] = xr[(i0 + tid) * 3 + 1];
        xi[tid][2] = xr[(i0 + tid) * 3 + 2];
        xj[tid][0] = xr[(j0 + tid) * 3 + 0];
        xj[tid][1] = xr[(j0 + tid) * 3 + 1];
        xj[tid][2] = xr[(j0 + tid) * 3 + 2];
    }
    if (tid < NBINS) pwh[tid] = pw[tid * HH + h];
    __syncthreads();

    int tx = tid & 15, ty = tid >> 4;
    float acc[4][4];
#pragma unroll
    for (int i = 0; i < 4; ++i)
#pragma unroll
        for (int j = 0; j < 4; ++j) acc[i][j] = 0.0f;
#pragma unroll
    for (int k = 0; k < 32; ++k) {
        float a[4], b[4];
#pragma unroll
        for (int i = 0; i < 4; ++i) a[i] = Qs[k * 65 + ty + 16 * i];
#pragma unroll
        for (int j = 0; j < 4; ++j) b[j] = Ks[k * 65 + tx + 16 * j];
#pragma unroll
        for (int i = 0; i < 4; ++i)
#pragma unroll
            for (int j = 0; j < 4; ++j) acc[i][j] += a[i] * b[j];
    }
    float wd = 1.0f / (1.0f + expf(-wdl[h]));
    float ie = 1.0f / eps[h];
    const float s32 = 0.17677669529663687f;  // 1/sqrt(32)
#pragma unroll
    for (int ii = 0; ii < 4; ++ii) {
        int il = ty + 16 * ii, i = i0 + il;
#pragma unroll
        for (int jj = 0; jj < 4; ++jj) {
            int jl = tx + 16 * jj, j = j0 + jl;
            int bn = bins[i * NN + j];
            float d0 = xi[il][0] - xj[jl][0];
            float d1 = xi[il][1] - xj[jl][1];
            float d2c = xi[il][2] - xj[jl][2];
            float dd = d0 * d0 + d1 * d1 + d2c * d2c;
            float logit = acc[ii][jj] * s32 + pwh[bn] - wd * dd * 0.01f;
            float lk = (mi[il] * mj[jl] > 0.0f) ? logit * ie : -1e9f;
            g_buf[OFF_LOGK + (h * NN + i) * NN + j] = lk;
        }
    }
}

// ---------------------------------------------------------------------------
__global__ void skprep_kernel(const float* __restrict__ mu, const float* __restrict__ nu,
                              const float* __restrict__ lup, const float* __restrict__ lvp) {
    int idx = blockIdx.x * 256 + threadIdx.x;
    if (idx >= HH * NN) return;
    g_buf[OFF_LOGMU + idx] = logf(fmaxf(mu[idx], 1e-8f));
    g_buf[OFF_LOGNU + idx] = logf(fmaxf(nu[idx], 1e-8f));
    g_buf[OFF_U + idx] = lup[idx];
    g_buf[OFF_V2 + idx] = lvp[idx];
}

// log_u[h,i] = fi*(log_mu - LSE_j(logK[h,i,j] + log_v[h,j]))
// One warp per row; row cached in 32 registers/lane; exact two-pass LSE.
__global__ void __launch_bounds__(256) sk_u_kernel(const float* __restrict__ eps) {
    __shared__ float sv[NN];
    int h = blockIdx.y;
    for (int t = threadIdx.x; t < NN; t += 256) sv[t] = g_buf[OFF_V2 + h * NN + t];
    __syncthreads();
    int w = threadIdx.x >> 5, lane = threadIdx.x & 31;
    int i = blockIdx.x * 8 + w;
    const float4* row = (const float4*)(g_buf + OFF_LOGK + (h * NN + i) * NN);
    const float4* svv = (const float4*)sv;
    float x[32];
    float m = -INFINITY;
#pragma unroll
    for (int q = 0; q < 8; ++q) {
        float4 a = row[q * 32 + lane];
        float4 b = svv[q * 32 + lane];
        x[q * 4 + 0] = a.x + b.x;
        x[q * 4 + 1] = a.y + b.y;
        x[q * 4 + 2] = a.z + b.z;
        x[q * 4 + 3] = a.w + b.w;
        m = fmaxf(m, fmaxf(fmaxf(x[q * 4 + 0], x[q * 4 + 1]),
                           fmaxf(x[q * 4 + 2], x[q * 4 + 3])));
    }
#pragma unroll
    for (int o = 16; o; o >>= 1) m = fmaxf(m, __shfl_xor_sync(0xffffffffu, m, o));
    float s = 0.0f;
#pragma unroll
    for (int k = 0; k < 32; ++k) s += __expf(x[k] - m);
#pragma unroll
    for (int o = 16; o; o >>= 1) s += __shfl_xor_sync(0xffffffffu, s, o);
    if (lane == 0) {
        float fi = 1.0f / (1.0f + eps[h]);
        g_buf[OFF_U + h * NN + i] = fi * (g_buf[OFF_LOGMU + h * NN + i] - (m + logf(s)));
    }
}

// log_v[h,j] = fi*(log_nu - LSE_i(logK[h,i,j] + log_u[h,i]))
__global__ void sk_v_kernel(const float* __restrict__ eps) {
    __shared__ float su[NN];
    __shared__ float rm[8][33], rsum[8][33];
    int h = blockIdx.y;
    for (int t = threadIdx.x; t < NN; t += 256) su[t] = g_buf[OFF_U + h * NN + t];
    __syncthreads();
    int jx = threadIdx.x & 31, sy = threadIdx.x >> 5;
    int j = blockIdx.x * 32 + jx;
    const float* col = g_buf + OFF_LOGK + h * NN * NN + j;
    float m = -INFINITY, s = 0.0f;
    int i0 = sy * 128;
#pragma unroll 4
    for (int t = 0; t < 128; ++t) {
        int i = i0 + t;
        float x = col[i * NN] + su[i];
        if (x > m) { s *= __expf(m - x); m = x; }
        s += __expf(x - m);
    }
    rm[sy][jx] = m; rsum[sy][jx] = s;
    __syncthreads();
    if (sy == 0) {
        float M = m, S = s;
#pragma unroll
        for (int k = 1; k < 8; ++k) {
            float mo = rm[k][jx], so = rsum[k][jx];
            float nm = fmaxf(M, mo);
            S = S * __expf(M - nm) + so * __expf(mo - nm);
            M = nm;
        }
        float fi = 1.0f / (1.0f + eps[h]);
        g_buf[OFF_V2 + h * NN + j] = fi * (g_buf[OFF_LOGNU + h * NN + j] - (M + logf(S)));
    }
}

// ---------------------------------------------------------------------------
// Pack Vx[h][j][c]: c<32 -> V head slice, c=32..34 -> x_res
__global__ void pack_kernel(const float* __restrict__ xr) {
    int idx = blockIdx.x * 256 + threadIdx.x;
    if (idx >= HH * NN * 35) return;
    int c = idx % 35;
    int hj = idx / 35;
    int j = hj & (NN - 1);
    int h = hj >> 10;
    float v = (c < 32) ? g_buf[OFF_V + j * DD + h * DH + c] : xr[j * 3 + (c - 32)];
    g_buf[OFF_VXP + idx] = v;
}

// Fused: P=exp(logK+u+v), rowsum clip, attn = Pn@V * sigmoid(G), x_cent = Pn@x_res.
// 1024 blocks = 16 heads x 64 row-blocks of 16 rows. Warp handles 2 rows.
__global__ void __launch_bounds__(256, 2) attn_kernel() {
    __shared__ float sVx[256 * 36];
    __shared__ float sv[256];
    int h = blockIdx.x >> 6;
    int w = threadIdx.x >> 5, lane = threadIdx.x & 31;
    int i0 = (blockIdx.x & 63) * 16 + w * 2;
    float uu0 = g_buf[OFF_U + h * NN + i0 + 0];
    float uu1 = g_buf[OFF_U + h * NN + i0 + 1];
    const float* lk0 = g_buf + OFF_LOGK + (h * NN + i0) * NN;

    for (int t = threadIdx.x; t < 256; t += 256) sVx[t * 36 + 35] = 0.0f;

    float acc[2][36];
#pragma unroll
    for (int r = 0; r < 2; ++r)
#pragma unroll
        for (int c = 0; c < 36; ++c) acc[r][c] = 0.0f;
    float rs0 = 0.f, rs1 = 0.f;

    for (int cb = 0; cb < 4; ++cb) {
        int jb = cb * 256;
        __syncthreads();
        const float* src = g_buf + OFF_VXP + (h * NN + jb) * 35;
        for (int t = threadIdx.x; t < 256 * 35; t += 256) {
            int jo = t / 35, c = t - jo * 35;
            sVx[jo * 36 + c] = src[t];
        }
        sv[threadIdx.x] = g_buf[OFF_V2 + h * NN + jb + threadIdx.x];
        __syncthreads();
#pragma unroll 1
        for (int s = 0; s < 8; ++s) {
            int jl = s * 32 + lane;
            int j = jb + jl;
            float vj = sv[jl];
            float p0 = __expf(lk0[j] + uu0 + vj);
            float p1 = __expf(lk0[NN + j] + uu1 + vj);
            rs0 += p0; rs1 += p1;
            const float4* vp = (const float4*)(sVx + jl * 36);
#pragma unroll
            for (int c4 = 0; c4 < 9; ++c4) {
                float4 vv = vp[c4];
                acc[0][c4 * 4 + 0] += p0 * vv.x; acc[0][c4 * 4 + 1] += p0 * vv.y;
                acc[0][c4 * 4 + 2] += p0 * vv.z; acc[0][c4 * 4 + 3] += p0 * vv.w;
                acc[1][c4 * 4 + 0] += p1 * vv.x; acc[1][c4 * 4 + 1] += p1 * vv.y;
                acc[1][c4 * 4 + 2] += p1 * vv.z; acc[1][c4 * 4 + 3] += p1 * vv.w;
            }
        }
    }

    float rsv[2] = {rs0, rs1};
#pragma unroll
    for (int r = 0; r < 2; ++r) {
        float t = rsv[r];
#pragma unroll
        for (int o = 16; o; o >>= 1) t += __shfl_xor_sync(0xffffffffu, t, o);
        rsv[r] = fmaxf(t, 1e-8f);
    }
#pragma unroll
    for (int r = 0; r < 2; ++r) {
        int i = i0 + r;
        float inv = 1.0f / rsv[r];
#pragma unroll
        for (int c = 0; c < 35; ++c) {
            float a = acc[r][c];
#pragma unroll
            for (int o = 16; o; o >>= 1) a += __shfl_xor_sync(0xffffffffu, a, o);
            if (c < 32) {
                if (lane == c) {
                    float g = g_buf[OFF_G + i * DD + h * DH + c];
                    float sg = 1.0f / (1.0f + __expf(-g));
                    g_buf[OFF_ATTN + i * DD + h * DH + c] = a * inv * sg;
                }
            } else {
                if (lane == c - 32) {
                    g_buf[OFF_XC + (h * NN + i) * 3 + (c - 32)] = a * inv;
                }
            }
        }
    }
}

// ---------------------------------------------------------------------------
__global__ void xupd_kernel(const float* __restrict__ xr, const float* __restrict__ mask,
                            const float* __restrict__ gamma, float* __restrict__ out) {
    int i = blockIdx.x * 256 + threadIdx.x;
    if (i >= NN) return;
    float x0 = xr[i * 3 + 0], x1 = xr[i * 3 + 1], x2 = xr[i * 3 + 2];
    float a0 = 0.f, a1 = 0.f, a2 = 0.f;
#pragma unroll
    for (int h = 0; h < HH; ++h) {
        float th = tanhf(gamma[h]) * (1.0f / HH);
        const float* xc = g_buf + OFF_XC + (h * NN + i) * 3;
        a0 += th * (x0 - xc[0]);
        a1 += th * (x1 - xc[1]);
        a2 += th * (x2 - xc[2]);
    }
    float mk = mask[i];
    out[i * 3 + 0] = x0 + a0 * mk;
    out[i * 3 + 1] = x1 + a1 * mk;
    out[i * 3 + 2] = x2 + a2 * mk;
}

__global__ void copyuv_kernel(float* __restrict__ out) {
    int idx = blockIdx.x * 256 + threadIdx.x;
    if (idx >= HH * NN) return;
    out[OUT_U + idx] = g_buf[OFF_U + idx];
    out[OUT_V + idx] = g_buf[OFF_V2 + idx];
}

__global__ void silu_kernel() {
    int idx = blockIdx.x * 256 + threadIdx.x;
    if (idx >= NN * 4 * DD) return;
    float a = g_buf[OFF_FFA + idx];
    float b = g_buf[OFF_FFB + idx];
    g_buf[OFF_FFG + idx] = a * b / (1.0f + __expf(-a));
}

// ---------------------------------------------------------------------------
extern "C" void kernel_launch(void* const* d_in, const int* in_sizes, int n_in,
                              void* d_out, int out_size) {
    const float* h    = (const float*)d_in[0];
    const float* xres = (const float*)d_in[1];
    const float* mu   = (const float*)d_in[2];
    const float* nu   = (const float*)d_in[3];
    const float* lup  = (const float*)d_in[4];
    const float* lvp  = (const float*)d_in[5];
    const float* mask = (const float*)d_in[6];
    const float* lnw  = (const float*)d_in[7];
    const float* lnb  = (const float*)d_in[8];
    const float* wq   = (const float*)d_in[9];
    const float* wk   = (const float*)d_in[10];
    const float* wv   = (const float*)d_in[11];
    const float* wg   = (const float*)d_in[12];
    const float* wo   = (const float*)d_in[13];
    const float* gamma= (const float*)d_in[14];
    const float* pw   = (const float*)d_in[15];
    const float* wdl  = (const float*)d_in[16];
    const float* lnfw = (const float*)d_in[17];
    const float* lnfb = (const float*)d_in[18];
    const float* w1   = (const float*)d_in[19];
    const float* w3   = (const float*)d_in[20];
    const float* w2   = (const float*)d_in[21];
    const int*   bins = (const int*)d_in[22];
    const float* eps  = (const float*)d_in[23];
    float* out = (float*)d_out;

    // 1. pre-LN
    ln_kernel<<<NN, 256>>>(h, 0, lnw, lnb, OFF_HN);

    // 2. fused Q|K|V|G projection: N=2048, segments land at OFF_Q..OFF_G
    gemm_kernel<128><<<dim3(32, 8), 256>>>(OFF_HN, wq, wk, wv, wg, DD,
                                           OFF_Q, 0, 0, -1, 0, NN, DD);

    // 3. per-head plain LN on Q, K
    headln_kernel<<<2048, 256>>>(OFF_Q);
    headln_kernel<<<2048, 256>>>(OFF_K);

    // 4. logK
    logk_kernel<<<dim3(16, 16, 16), 256>>>(bins, pw, wdl, eps, mask, xres);

    // 5. Sinkhorn
    skprep_kernel<<<64, 256>>>(mu, nu, lup, lvp);
    for (int it = 0; it < 20; ++it) {
        sk_u_kernel<<<dim3(128, 16), 256>>>(eps);
        sk_v_kernel<<<dim3(32, 16), 256>>>(eps);
    }
    copyuv_kernel<<<64, 256>>>(out);

    // 6. fused transport-plan attention + centroids
    pack_kernel<<<(HH * NN * 35 + 255) / 256, 256>>>(xres);
    attn_kernel<<<1024, 256>>>();
    xupd_kernel<<<4, 256>>>(xres, mask, gamma, out + OUT_X);

    // 7. output projection + residual
    gemm_kernel<64><<<dim3(8, 16), 256>>>(OFF_ATTN, wo, wo, wo, wo, DD,
                                          OFF_HMID, 0, h, -1, mask, NN, DD);

    // 8. FFN
    ln_kernel<<<NN, 256>>>(0, OFF_HMID, lnfw, lnfb, OFF_H2);
    gemm_kernel<128><<<dim3(64, 8), 256>>>(OFF_H2, w1, w3, w1, w1, 4 * DD,
                                           OFF_FFA, 0, 0, -1, 0, NN, DD);
    silu_kernel<<<(NN * 4 * DD + 255) / 256, 256>>>();
    gemm_kernel<64><<<dim3(8, 16), 256>>>(OFF_FFG, w2, w2, w2, w2, DD,
                                          0, out + OUT_H, 0, OFF_HMID, mask, NN, 4 * DD);
}

// round 6
// speedup vs baseline: 1.7601x; 1.1625x over previous
#include <cuda_runtime.h>
#include <math.h>
#include <stdint.h>

#define NN 1024
#define DD 512
#define HH 16
#define DH 32
#define NBINS 68

// ---- scratch layout (float offsets into one big __device__ buffer) ----
#define OFF_HN     0
#define OFF_Q      524288
#define OFF_K      1048576
#define OFF_V      1572864
#define OFF_G      2097152
#define OFF_LOGK   2621440
#define OFF_LOGMU  19398656
#define OFF_LOGNU  19415040
#define OFF_U      19431424
#define OFF_V2     19447808
#define OFF_VXP    19464192
#define OFF_ATTN   20037632
#define OFF_XC     20561920
#define OFF_HMID   20611072
#define OFF_H2     21135360
#define OFF_FFA    21659648
#define OFF_FFB    23756800
#define OFF_FFG    25853952
#define BUF_TOTAL  27951104

__device__ float g_buf[BUF_TOTAL];

// Output layout: [h | x_res | log_u | log_v]
#define OUT_H 0
#define OUT_X 524288
#define OUT_U 527360
#define OUT_V 543744

// ---------------------------------------------------------------------------
__device__ __forceinline__ float tf32r(float x) {
    uint32_t u;
    asm("cvt.rna.tf32.f32 %0, %1;" : "=r"(u) : "f"(x));
    return __uint_as_float(u);
}

__device__ __forceinline__ void mma_tf32(float* d, const uint32_t* a, const uint32_t* b) {
    asm volatile(
        "mma.sync.aligned.m16n8k8.row.col.f32.tf32.tf32.f32 "
        "{%0,%1,%2,%3}, {%4,%5,%6,%7}, {%8,%9}, {%0,%1,%2,%3};"
        : "+f"(d[0]), "+f"(d[1]), "+f"(d[2]), "+f"(d[3])
        : "r"(a[0]), "r"(a[1]), "r"(a[2]), "r"(a[3]), "r"(b[0]), "r"(b[1]));
}

// ---------------------------------------------------------------------------
// LayerNorm over last dim D=512. One block per row, 256 threads.
__global__ void ln_kernel(const float* __restrict__ inExt, int inOff,
                          const float* __restrict__ w, const float* __restrict__ b,
                          int outOff) {
    const float* in = inExt ? inExt : (g_buf + inOff);
    int row = blockIdx.x, tid = threadIdx.x;
    __shared__ float red[256];
    float x0 = in[row * DD + tid];
    float x1 = in[row * DD + 256 + tid];
    red[tid] = x0 + x1;
    __syncthreads();
    for (int o = 128; o; o >>= 1) { if (tid < o) red[tid] += red[tid + o]; __syncthreads(); }
    float m = red[0] * (1.0f / DD);
    __syncthreads();
    float d0 = x0 - m, d1 = x1 - m;
    red[tid] = d0 * d0 + d1 * d1;
    __syncthreads();
    for (int o = 128; o; o >>= 1) { if (tid < o) red[tid] += red[tid + o]; __syncthreads(); }
    float var = red[0] * (1.0f / DD);
    float rs = rsqrtf(var + 1e-5f);
    float* out = g_buf + outOff;
    out[row * DD + tid]       = d0 * rs * w[tid]       + b[tid];
    out[row * DD + 256 + tid] = d1 * rs * w[tid + 256] + b[tid + 256];
}

// ---------------------------------------------------------------------------
// TF32 tensor-core GEMM: C[M,N] = A[M,K] @ B[N,K]^T, up to 4 weight matrices
// as consecutive nPerW-wide output segments. Optional epilogue
// out = res + C*mask[row]. 256 threads = 8 warps (2 x 4), warp tile (BM/2 x BN/4).
template<int BM, int BN>
__global__ void __launch_bounds__(256) tgemm_kernel(
    int aOff, const float* __restrict__ B0, const float* __restrict__ B1,
    const float* __restrict__ B2, const float* __restrict__ B3,
    int nPerW, int cOff, float* __restrict__ outExt,
    const float* __restrict__ resExt, int resOff,
    const float* __restrict__ mask, int M, int K) {
    constexpr int BK = 16;
    constexpr int WM = BM / 2, WN = BN / 4;
    constexpr int MT = WM / 16, NT = WN / 8;
    __shared__ float As[BM][BK + 4];
    __shared__ float Bs[BN][BK + 4];
    const float* A = g_buf + aOff;
    int m0 = blockIdx.y * BM, n0 = blockIdx.x * BN;
    int widx = n0 / nPerW;
    const float* Bw = (widx == 0) ? B0 : (widx == 1) ? B1 : (widx == 2) ? B2 : B3;
    int nloc0 = n0 - widx * nPerW;

    int tid = threadIdx.x, lane = tid & 31, wid = tid >> 5;
    int warpM = wid >> 2, warpN = wid & 3;

    float d[MT][NT][4];
#pragma unroll
    for (int mt = 0; mt < MT; ++mt)
#pragma unroll
        for (int nt = 0; nt < NT; ++nt)
#pragma unroll
            for (int q = 0; q < 4; ++q) d[mt][nt][q] = 0.0f;

    for (int k0 = 0; k0 < K; k0 += BK) {
#pragma unroll
        for (int t0 = 0; t0 < BM * 4; t0 += 256) {
            int t = t0 + tid;
            int r = t >> 2, kq = (t & 3) << 2;
            float4 v = *(const float4*)&A[(m0 + r) * K + k0 + kq];
            float4 c = make_float4(tf32r(v.x), tf32r(v.y), tf32r(v.z), tf32r(v.w));
            *(float4*)&As[r][kq] = c;
        }
#pragma unroll
        for (int t0 = 0; t0 < BN * 4; t0 += 256) {
            int t = t0 + tid;
            int r = t >> 2, kq = (t & 3) << 2;
            float4 v = *(const float4*)&Bw[(nloc0 + r) * K + k0 + kq];
            float4 c = make_float4(tf32r(v.x), tf32r(v.y), tf32r(v.z), tf32r(v.w));
            *(float4*)&Bs[r][kq] = c;
        }
        __syncthreads();
#pragma unroll
        for (int ks = 0; ks < 2; ++ks) {
            int kb = ks * 8;
            uint32_t a[MT][4], b[NT][2];
#pragma unroll
            for (int mt = 0; mt < MT; ++mt) {
                int r = warpM * WM + mt * 16 + (lane >> 2);
                int c = kb + (lane & 3);
                a[mt][0] = __float_as_uint(As[r][c]);
                a[mt][1] = __float_as_uint(As[r + 8][c]);
                a[mt][2] = __float_as_uint(As[r][c + 4]);
                a[mt][3] = __float_as_uint(As[r + 8][c + 4]);
            }
#pragma unroll
            for (int nt = 0; nt < NT; ++nt) {
                int r = warpN * WN + nt * 8 + (lane >> 2);
                int c = kb + (lane & 3);
                b[nt][0] = __float_as_uint(Bs[r][c]);
                b[nt][1] = __float_as_uint(Bs[r][c + 4]);
            }
#pragma unroll
            for (int mt = 0; mt < MT; ++mt)
#pragma unroll
                for (int nt = 0; nt < NT; ++nt) mma_tf32(d[mt][nt], a[mt], b[nt]);
        }
        __syncthreads();
    }

    float* outp = (outExt ? outExt : (g_buf + cOff)) + (long)widx * M * nPerW;
    const float* resp = resExt ? resExt : (resOff >= 0 ? (g_buf + resOff) : (const float*)0);
#pragma unroll
    for (int mt = 0; mt < MT; ++mt) {
        int row0 = m0 + warpM * WM + mt * 16 + (lane >> 2);
#pragma unroll
        for (int nt = 0; nt < NT; ++nt) {
            int col = nloc0 + warpN * WN + nt * 8 + (lane & 3) * 2;
#pragma unroll
            for (int half = 0; half < 2; ++half) {
                int row = row0 + half * 8;
                float2 v = make_float2(d[mt][nt][half * 2], d[mt][nt][half * 2 + 1]);
                if (resp) {
                    float mk = mask ? mask[row] : 1.0f;
                    float2 r2 = *(const float2*)&resp[row * nPerW + col];
                    v.x = r2.x + v.x * mk;
                    v.y = r2.y + v.y * mk;
                }
                *(float2*)&outp[row * nPerW + col] = v;
            }
        }
    }
}

// ---------------------------------------------------------------------------
// Per-head plain LN over DH=32 (one warp per (token,head) vector), in place.
__global__ void headln_kernel(int off) {
    int gid = blockIdx.x * 8 + (threadIdx.x >> 5);
    int lane = threadIdx.x & 31;
    int i = gid >> 4, h = gid & 15;
    float* p = g_buf + off + i * DD + h * DH + lane;
    float x = *p;
    float s = x;
#pragma unroll
    for (int o = 16; o; o >>= 1) s += __shfl_xor_sync(0xffffffffu, s, o);
    float m = s * (1.0f / DH);
    float d = x - m;
    float v = d * d;
#pragma unroll
    for (int o = 16; o; o >>= 1) v += __shfl_xor_sync(0xffffffffu, v, o);
    float var = v * (1.0f / DH);
    *p = d * rsqrtf(var + 1e-5f);
}

// ---------------------------------------------------------------------------
// logK[h,i,j] = pair_mask ? (QK/sqrt(32) + bias - sigmoid(wdl)*d2/100)/eps_h : -1e9
__global__ void logk_kernel(const int* __restrict__ bins, const float* __restrict__ pw,
                            const float* __restrict__ wdl, const float* __restrict__ eps,
                            const float* __restrict__ mask, const float* __restrict__ xr) {
    __shared__ float Qs[32 * 65], Ks[32 * 65];
    __shared__ float xi[64][3], xj[64][3], mi[64], mj[64], pwh[NBINS];
    int h = blockIdx.z, i0 = blockIdx.y * 64, j0 = blockIdx.x * 64;
    int tid = threadIdx.x;
    for (int t = tid; t < 64 * 32; t += 256) {
        int r = t >> 5, k = t & 31;
        Qs[k * 65 + r] = g_buf[OFF_Q + (i0 + r) * DD + h * DH + k];
        Ks[k * 65 + r] = g_buf[OFF_K + (j0 + r) * DD + h * DH + k];
    }
    if (tid < 64) {
        mi[tid] = mask[i0 + tid];
        mj[tid] = mask[j0 + tid];
        xi[tid][0] = xr[(i0 + tid) * 3 + 0];
        xi[tid][1] = xr[(i0 + tid) * 3 + 1];
        xi[tid][2] = xr[(i0 + tid) * 3 + 2];
        xj[tid][0] = xr[(j0 + tid) * 3 + 0];
        xj[tid][1] = xr[(j0 + tid) * 3 + 1];
        xj[tid][2] = xr[(j0 + tid) * 3 + 2];
    }
    if (tid < NBINS) pwh[tid] = pw[tid * HH + h];
    __syncthreads();

    int tx = tid & 15, ty = tid >> 4;
    float acc[4][4];
#pragma unroll
    for (int i = 0; i < 4; ++i)
#pragma unroll
        for (int j = 0; j < 4; ++j) acc[i][j] = 0.0f;
#pragma unroll
    for (int k = 0; k < 32; ++k) {
        float a[4], b[4];
#pragma unroll
        for (int i = 0; i < 4; ++i) a[i] = Qs[k * 65 + ty + 16 * i];
#pragma unroll
        for (int j = 0; j < 4; ++j) b[j] = Ks[k * 65 + tx + 16 * j];
#pragma unroll
        for (int i = 0; i < 4; ++i)
#pragma unroll
            for (int j = 0; j < 4; ++j) acc[i][j] += a[i] * b[j];
    }
    float wd = 1.0f / (1.0f + expf(-wdl[h]));
    float ie = 1.0f / eps[h];
    const float s32 = 0.17677669529663687f;  // 1/sqrt(32)
#pragma unroll
    for (int ii = 0; ii < 4; ++ii) {
        int il = ty + 16 * ii, i = i0 + il;
#pragma unroll
        for (int jj = 0; jj < 4; ++jj) {
            int jl = tx + 16 * jj, j = j0 + jl;
            int bn = bins[i * NN + j];
            float d0 = xi[il][0] - xj[jl][0];
            float d1 = xi[il][1] - xj[jl][1];
            float d2c = xi[il][2] - xj[jl][2];
            float dd = d0 * d0 + d1 * d1 + d2c * d2c;
            float logit = acc[ii][jj] * s32 + pwh[bn] - wd * dd * 0.01f;
            float lk = (mi[il] * mj[jl] > 0.0f) ? logit * ie : -1e9f;
            g_buf[OFF_LOGK + (h * NN + i) * NN + j] = lk;
        }
    }
}

// ---------------------------------------------------------------------------
__global__ void skprep_kernel(const float* __restrict__ mu, const float* __restrict__ nu,
                              const float* __restrict__ lup, const float* __restrict__ lvp) {
    int idx = blockIdx.x * 256 + threadIdx.x;
    if (idx >= HH * NN) return;
    g_buf[OFF_LOGMU + idx] = logf(fmaxf(mu[idx], 1e-8f));
    g_buf[OFF_LOGNU + idx] = logf(fmaxf(nu[idx], 1e-8f));
    g_buf[OFF_U + idx] = lup[idx];
    g_buf[OFF_V2 + idx] = lvp[idx];
}

// log_u[h,i] = fi*(log_mu - LSE_j(logK[h,i,j] + log_v[h,j]))
// One warp per row; row cached in 32 registers/lane; exact two-pass LSE.
__global__ void __launch_bounds__(256) sk_u_kernel(const float* __restrict__ eps) {
    __shared__ float sv[NN];
    int h = blockIdx.y;
    for (int t = threadIdx.x; t < NN; t += 256) sv[t] = g_buf[OFF_V2 + h * NN + t];
    __syncthreads();
    int w = threadIdx.x >> 5, lane = threadIdx.x & 31;
    int i = blockIdx.x * 8 + w;
    const float4* row = (const float4*)(g_buf + OFF_LOGK + (h * NN + i) * NN);
    const float4* svv = (const float4*)sv;
    float x[32];
    float m = -INFINITY;
#pragma unroll
    for (int q = 0; q < 8; ++q) {
        float4 a = row[q * 32 + lane];
        float4 b = svv[q * 32 + lane];
        x[q * 4 + 0] = a.x + b.x;
        x[q * 4 + 1] = a.y + b.y;
        x[q * 4 + 2] = a.z + b.z;
        x[q * 4 + 3] = a.w + b.w;
        m = fmaxf(m, fmaxf(fmaxf(x[q * 4 + 0], x[q * 4 + 1]),
                           fmaxf(x[q * 4 + 2], x[q * 4 + 3])));
    }
#pragma unroll
    for (int o = 16; o; o >>= 1) m = fmaxf(m, __shfl_xor_sync(0xffffffffu, m, o));
    float s = 0.0f;
#pragma unroll
    for (int k = 0; k < 32; ++k) s += __expf(x[k] - m);
#pragma unroll
    for (int o = 16; o; o >>= 1) s += __shfl_xor_sync(0xffffffffu, s, o);
    if (lane == 0) {
        float fi = 1.0f / (1.0f + eps[h]);
        g_buf[OFF_U + h * NN + i] = fi * (g_buf[OFF_LOGMU + h * NN + i] - (m + logf(s)));
    }
}

// log_v[h,j] = fi*(log_nu - LSE_i(logK[h,i,j] + log_u[h,i]))
__global__ void sk_v_kernel(const float* __restrict__ eps) {
    __shared__ float su[NN];
    __shared__ float rm[8][33], rsum[8][33];
    int h = blockIdx.y;
    for (int t = threadIdx.x; t < NN; t += 256) su[t] = g_buf[OFF_U + h * NN + t];
    __syncthreads();
    int jx = threadIdx.x & 31, sy = threadIdx.x >> 5;
    int j = blockIdx.x * 32 + jx;
    const float* col = g_buf + OFF_LOGK + h * NN * NN + j;
    float m = -INFINITY, s = 0.0f;
    int i0 = sy * 128;
#pragma unroll 4
    for (int t = 0; t < 128; ++t) {
        int i = i0 + t;
        float x = col[i * NN] + su[i];
        if (x > m) { s *= __expf(m - x); m = x; }
        s += __expf(x - m);
    }
    rm[sy][jx] = m; rsum[sy][jx] = s;
    __syncthreads();
    if (sy == 0) {
        float M = m, S = s;
#pragma unroll
        for (int k = 1; k < 8; ++k) {
            float mo = rm[k][jx], so = rsum[k][jx];
            float nm = fmaxf(M, mo);
            S = S * __expf(M - nm) + so * __expf(mo - nm);
            M = nm;
        }
        float fi = 1.0f / (1.0f + eps[h]);
        g_buf[OFF_V2 + h * NN + j] = fi * (g_buf[OFF_LOGNU + h * NN + j] - (M + logf(S)));
    }
}

// ---------------------------------------------------------------------------
// Pack Vx[h][j][c]: c<32 -> V head slice, c=32..34 -> x_res
__global__ void pack_kernel(const float* __restrict__ xr) {
    int idx = blockIdx.x * 256 + threadIdx.x;
    if (idx >= HH * NN * 35) return;
    int c = idx % 35;
    int hj = idx / 35;
    int j = hj & (NN - 1);
    int h = hj >> 10;
    float v = (c < 32) ? g_buf[OFF_V + j * DD + h * DH + c] : xr[j * 3 + (c - 32)];
    g_buf[OFF_VXP + idx] = v;
}

// Fused: P=exp(logK+u+v), rowsum clip, attn = Pn@V * sigmoid(G), x_cent = Pn@x_res.
// 1024 blocks = 16 heads x 64 row-blocks of 16 rows. Warp handles 2 rows.
__global__ void __launch_bounds__(256, 2) attn_kernel() {
    __shared__ float sVx[256 * 36];
    __shared__ float sv[256];
    int h = blockIdx.x >> 6;
    int w = threadIdx.x >> 5, lane = threadIdx.x & 31;
    int i0 = (blockIdx.x & 63) * 16 + w * 2;
    float uu0 = g_buf[OFF_U + h * NN + i0 + 0];
    float uu1 = g_buf[OFF_U + h * NN + i0 + 1];
    const float* lk0 = g_buf + OFF_LOGK + (h * NN + i0) * NN;

    for (int t = threadIdx.x; t < 256; t += 256) sVx[t * 36 + 35] = 0.0f;

    float acc[2][36];
#pragma unroll
    for (int r = 0; r < 2; ++r)
#pragma unroll
        for (int c = 0; c < 36; ++c) acc[r][c] = 0.0f;
    float rs0 = 0.f, rs1 = 0.f;

    for (int cb = 0; cb < 4; ++cb) {
        int jb = cb * 256;
        __syncthreads();
        const float* src = g_buf + OFF_VXP + (h * NN + jb) * 35;
        for (int t = threadIdx.x; t < 256 * 35; t += 256) {
            int jo = t / 35, c = t - jo * 35;
            sVx[jo * 36 + c] = src[t];
        }
        sv[threadIdx.x] = g_buf[OFF_V2 + h * NN + jb + threadIdx.x];
        __syncthreads();
#pragma unroll 1
        for (int s = 0; s < 8; ++s) {
            int jl = s * 32 + lane;
            int j = jb + jl;
            float vj = sv[jl];
            float p0 = __expf(lk0[j] + uu0 + vj);
            float p1 = __expf(lk0[NN + j] + uu1 + vj);
            rs0 += p0; rs1 += p1;
            const float4* vp = (const float4*)(sVx + jl * 36);
#pragma unroll
            for (int c4 = 0; c4 < 9; ++c4) {
                float4 vv = vp[c4];
                acc[0][c4 * 4 + 0] += p0 * vv.x; acc[0][c4 * 4 + 1] += p0 * vv.y;
                acc[0][c4 * 4 + 2] += p0 * vv.z; acc[0][c4 * 4 + 3] += p0 * vv.w;
                acc[1][c4 * 4 + 0] += p1 * vv.x; acc[1][c4 * 4 + 1] += p1 * vv.y;
                acc[1][c4 * 4 + 2] += p1 * vv.z; acc[1][c4 * 4 + 3] += p1 * vv.w;
            }
        }
    }

    float rsv[2] = {rs0, rs1};
#pragma unroll
    for (int r = 0; r < 2; ++r) {
        float t = rsv[r];
#pragma unroll
        for (int o = 16; o; o >>= 1) t += __shfl_xor_sync(0xffffffffu, t, o);
        rsv[r] = fmaxf(t, 1e-8f);
    }
#pragma unroll
    for (int r = 0; r < 2; ++r) {
        int i = i0 + r;
        float inv = 1.0f / rsv[r];
#pragma unroll
        for (int c = 0; c < 35; ++c) {
            float a = acc[r][c];
#pragma unroll
            for (int o = 16; o; o >>= 1) a += __shfl_xor_sync(0xffffffffu, a, o);
            if (c < 32) {
                if (lane == c) {
                    float g = g_buf[OFF_G + i * DD + h * DH + c];
                    float sg = 1.0f / (1.0f + __expf(-g));
                    g_buf[OFF_ATTN + i * DD + h * DH + c] = a * inv * sg;
                }
            } else {
                if (lane == c - 32) {
                    g_buf[OFF_XC + (h * NN + i) * 3 + (c - 32)] = a * inv;
                }
            }
        }
    }
}

// ---------------------------------------------------------------------------
__global__ void xupd_kernel(const float* __restrict__ xr, const float* __restrict__ mask,
                            const float* __restrict__ gamma, float* __restrict__ out) {
    int i = blockIdx.x * 256 + threadIdx.x;
    if (i >= NN) return;
    float x0 = xr[i * 3 + 0], x1 = xr[i * 3 + 1], x2 = xr[i * 3 + 2];
    float a0 = 0.f, a1 = 0.f, a2 = 0.f;
#pragma unroll
    for (int h = 0; h < HH; ++h) {
        float th = tanhf(gamma[h]) * (1.0f / HH);
        const float* xc = g_buf + OFF_XC + (h * NN + i) * 3;
        a0 += th * (x0 - xc[0]);
        a1 += th * (x1 - xc[1]);
        a2 += th * (x2 - xc[2]);
    }
    float mk = mask[i];
    out[i * 3 + 0] = x0 + a0 * mk;
    out[i * 3 + 1] = x1 + a1 * mk;
    out[i * 3 + 2] = x2 + a2 * mk;
}

__global__ void copyuv_kernel(float* __restrict__ out) {
    int idx = blockIdx.x * 256 + threadIdx.x;
    if (idx >= HH * NN) return;
    out[OUT_U + idx] = g_buf[OFF_U + idx];
    out[OUT_V + idx] = g_buf[OFF_V2 + idx];
}

__global__ void silu_kernel() {
    int idx = blockIdx.x * 256 + threadIdx.x;
    if (idx >= NN * 4 * DD) return;
    float a = g_buf[OFF_FFA + idx];
    float b = g_buf[OFF_FFB + idx];
    g_buf[OFF_FFG + idx] = a * b / (1.0f + __expf(-a));
}

// ---------------------------------------------------------------------------
extern "C" void kernel_launch(void* const* d_in, const int* in_sizes, int n_in,
                              void* d_out, int out_size) {
    const float* h    = (const float*)d_in[0];
    const float* xres = (const float*)d_in[1];
    const float* mu   = (const float*)d_in[2];
    const float* nu   = (const float*)d_in[3];
    const float* lup  = (const float*)d_in[4];
    const float* lvp  = (const float*)d_in[5];
    const float* mask = (const float*)d_in[6];
    const float* lnw  = (const float*)d_in[7];
    const float* lnb  = (const float*)d_in[8];
    const float* wq   = (const float*)d_in[9];
    const float* wk   = (const float*)d_in[10];
    const float* wv   = (const float*)d_in[11];
    const float* wg   = (const float*)d_in[12];
    const float* wo   = (const float*)d_in[13];
    const float* gamma= (const float*)d_in[14];
    const float* pw   = (const float*)d_in[15];
    const float* wdl  = (const float*)d_in[16];
    const float* lnfw = (const float*)d_in[17];
    const float* lnfb = (const float*)d_in[18];
    const float* w1   = (const float*)d_in[19];
    const float* w3   = (const float*)d_in[20];
    const float* w2   = (const float*)d_in[21];
    const int*   bins = (const int*)d_in[22];
    const float* eps  = (const float*)d_in[23];
    float* out = (float*)d_out;

    // 1. pre-LN
    ln_kernel<<<NN, 256>>>(h, 0, lnw, lnb, OFF_HN);

    // 2. fused Q|K|V|G projection: N=2048, segments land at OFF_Q..OFF_G
    tgemm_kernel<128, 128><<<dim3(16, 8), 256>>>(OFF_HN, wq, wk, wv, wg, DD,
                                                 OFF_Q, 0, 0, -1, 0, NN, DD);

    // 3. per-head plain LN on Q, K
    headln_kernel<<<2048, 256>>>(OFF_Q);
    headln_kernel<<<2048, 256>>>(OFF_K);

    // 4. logK
    logk_kernel<<<dim3(16, 16, 16), 256>>>(bins, pw, wdl, eps, mask, xres);

    // 5. Sinkhorn
    skprep_kernel<<<64, 256>>>(mu, nu, lup, lvp);
    for (int it = 0; it < 20; ++it) {
        sk_u_kernel<<<dim3(128, 16), 256>>>(eps);
        sk_v_kernel<<<dim3(32, 16), 256>>>(eps);
    }
    copyuv_kernel<<<64, 256>>>(out);

    // 6. fused transport-plan attention + centroids
    pack_kernel<<<(HH * NN * 35 + 255) / 256, 256>>>(xres);
    attn_kernel<<<1024, 256>>>();
    xupd_kernel<<<4, 256>>>(xres, mask, gamma, out + OUT_X);

    // 7. output projection + residual
    tgemm_kernel<64, 64><<<dim3(8, 16), 256>>>(OFF_ATTN, wo, wo, wo, wo, DD,
                                               OFF_HMID, 0, h, -1, mask, NN, DD);

    // 8. FFN
    ln_kernel<<<NN, 256>>>(0, OFF_HMID, lnfw, lnfb, OFF_H2);
    tgemm_kernel<128, 128><<<dim3(32, 8), 256>>>(OFF_H2, w1, w3, w1, w1, 4 * DD,
                                                 OFF_FFA, 0, 0, -1, 0, NN, DD);
    silu_kernel<<<(NN * 4 * DD + 255) / 256, 256>>>();
    tgemm_kernel<64, 64><<<dim3(8, 16), 256>>>(OFF_FFG, w2, w2, w2, w2, DD,
                                               0, out + OUT_H, 0, OFF_HMID, mask, NN, 4 * DD);
}

// round 7
// speedup vs baseline: 2.1610x; 1.2278x over previous
#include <cuda_runtime.h>
#include <math.h>
#include <stdint.h>

#define NN 1024
#define DD 512
#define HH 16
#define DH 32
#define NBINS 68

// ---- scratch layout (float offsets into one big __device__ buffer) ----
#define OFF_HN     0
#define OFF_Q      524288
#define OFF_K      1048576
#define OFF_V      1572864
#define OFF_G      2097152
#define OFF_EK     2621440          /* E = exp(logK), 16*1024*1024 */
#define OFF_LOGMU  19398656
#define OFF_LOGNU  19415040
#define OFF_U      19431424
#define OFF_V2     19447808
#define OFF_VXP    19464192
#define OFF_ATTN   20037632
#define OFF_XC     20561920
#define OFF_HMID   20611072
#define OFF_H2     21135360
#define OFF_FFA    21659648
#define OFF_FFB    23756800
#define OFF_FFG    25853952
#define BUF_TOTAL  27951104

__device__ float g_buf[BUF_TOTAL];

// Output layout: [h | x_res | log_u | log_v]
#define OUT_H 0
#define OUT_X 524288
#define OUT_U 527360
#define OUT_V 543744

// ---------------------------------------------------------------------------
__device__ __forceinline__ float tf32r(float x) {
    uint32_t u;
    asm("cvt.rna.tf32.f32 %0, %1;" : "=r"(u) : "f"(x));
    return __uint_as_float(u);
}

__device__ __forceinline__ void mma_tf32(float* d, const uint32_t* a, const uint32_t* b) {
    asm volatile(
        "mma.sync.aligned.m16n8k8.row.col.f32.tf32.tf32.f32 "
        "{%0,%1,%2,%3}, {%4,%5,%6,%7}, {%8,%9}, {%0,%1,%2,%3};"
        : "+f"(d[0]), "+f"(d[1]), "+f"(d[2]), "+f"(d[3])
        : "r"(a[0]), "r"(a[1]), "r"(a[2]), "r"(a[3]), "r"(b[0]), "r"(b[1]));
}

// ---------------------------------------------------------------------------
// LayerNorm over last dim D=512. One block per row, 256 threads.
__global__ void ln_kernel(const float* __restrict__ inExt, int inOff,
                          const float* __restrict__ w, const float* __restrict__ b,
                          int outOff) {
    const float* in = inExt ? inExt : (g_buf + inOff);
    int row = blockIdx.x, tid = threadIdx.x;
    __shared__ float red[256];
    float x0 = in[row * DD + tid];
    float x1 = in[row * DD + 256 + tid];
    red[tid] = x0 + x1;
    __syncthreads();
    for (int o = 128; o; o >>= 1) { if (tid < o) red[tid] += red[tid + o]; __syncthreads(); }
    float m = red[0] * (1.0f / DD);
    __syncthreads();
    float d0 = x0 - m, d1 = x1 - m;
    red[tid] = d0 * d0 + d1 * d1;
    __syncthreads();
    for (int o = 128; o; o >>= 1) { if (tid < o) red[tid] += red[tid + o]; __syncthreads(); }
    float var = red[0] * (1.0f / DD);
    float rs = rsqrtf(var + 1e-5f);
    float* out = g_buf + outOff;
    out[row * DD + tid]       = d0 * rs * w[tid]       + b[tid];
    out[row * DD + 256 + tid] = d1 * rs * w[tid + 256] + b[tid + 256];
}

// ---------------------------------------------------------------------------
// TF32 tensor-core GEMM: C[M,N] = A[M,K] @ B[N,K]^T, up to 4 weight matrices
// as consecutive nPerW-wide output segments. Optional epilogue
// out = res + C*mask[row]. 256 threads = 8 warps (2 x 4), warp tile (BM/2 x BN/4).
template<int BM, int BN>
__global__ void __launch_bounds__(256) tgemm_kernel(
    int aOff, const float* __restrict__ B0, const float* __restrict__ B1,
    const float* __restrict__ B2, const float* __restrict__ B3,
    int nPerW, int cOff, float* __restrict__ outExt,
    const float* __restrict__ resExt, int resOff,
    const float* __restrict__ mask, int M, int K) {
    constexpr int BK = 16;
    constexpr int WM = BM / 2, WN = BN / 4;
    constexpr int MT = WM / 16, NT = WN / 8;
    __shared__ float As[BM][BK + 4];
    __shared__ float Bs[BN][BK + 4];
    const float* A = g_buf + aOff;
    int m0 = blockIdx.y * BM, n0 = blockIdx.x * BN;
    int widx = n0 / nPerW;
    const float* Bw = (widx == 0) ? B0 : (widx == 1) ? B1 : (widx == 2) ? B2 : B3;
    int nloc0 = n0 - widx * nPerW;

    int tid = threadIdx.x, lane = tid & 31, wid = tid >> 5;
    int warpM = wid >> 2, warpN = wid & 3;

    float d[MT][NT][4];
#pragma unroll
    for (int mt = 0; mt < MT; ++mt)
#pragma unroll
        for (int nt = 0; nt < NT; ++nt)
#pragma unroll
            for (int q = 0; q < 4; ++q) d[mt][nt][q] = 0.0f;

    for (int k0 = 0; k0 < K; k0 += BK) {
#pragma unroll
        for (int t0 = 0; t0 < BM * 4; t0 += 256) {
            int t = t0 + tid;
            int r = t >> 2, kq = (t & 3) << 2;
            float4 v = *(const float4*)&A[(m0 + r) * K + k0 + kq];
            float4 c = make_float4(tf32r(v.x), tf32r(v.y), tf32r(v.z), tf32r(v.w));
            *(float4*)&As[r][kq] = c;
        }
#pragma unroll
        for (int t0 = 0; t0 < BN * 4; t0 += 256) {
            int t = t0 + tid;
            int r = t >> 2, kq = (t & 3) << 2;
            float4 v = *(const float4*)&Bw[(nloc0 + r) * K + k0 + kq];
            float4 c = make_float4(tf32r(v.x), tf32r(v.y), tf32r(v.z), tf32r(v.w));
            *(float4*)&Bs[r][kq] = c;
        }
        __syncthreads();
#pragma unroll
        for (int ks = 0; ks < 2; ++ks) {
            int kb = ks * 8;
            uint32_t a[MT][4], b[NT][2];
#pragma unroll
            for (int mt = 0; mt < MT; ++mt) {
                int r = warpM * WM + mt * 16 + (lane >> 2);
                int c = kb + (lane & 3);
                a[mt][0] = __float_as_uint(As[r][c]);
                a[mt][1] = __float_as_uint(As[r + 8][c]);
                a[mt][2] = __float_as_uint(As[r][c + 4]);
                a[mt][3] = __float_as_uint(As[r + 8][c + 4]);
            }
#pragma unroll
            for (int nt = 0; nt < NT; ++nt) {
                int r = warpN * WN + nt * 8 + (lane >> 2);
                int c = kb + (lane & 3);
                b[nt][0] = __float_as_uint(Bs[r][c]);
                b[nt][1] = __float_as_uint(Bs[r][c + 4]);
            }
#pragma unroll
            for (int mt = 0; mt < MT; ++mt)
#pragma unroll
                for (int nt = 0; nt < NT; ++nt) mma_tf32(d[mt][nt], a[mt], b[nt]);
        }
        __syncthreads();
    }

    float* outp = (outExt ? outExt : (g_buf + cOff)) + (long)widx * M * nPerW;
    const float* resp = resExt ? resExt : (resOff >= 0 ? (g_buf + resOff) : (const float*)0);
#pragma unroll
    for (int mt = 0; mt < MT; ++mt) {
        int row0 = m0 + warpM * WM + mt * 16 + (lane >> 2);
#pragma unroll
        for (int nt = 0; nt < NT; ++nt) {
            int col = nloc0 + warpN * WN + nt * 8 + (lane & 3) * 2;
#pragma unroll
            for (int half = 0; half < 2; ++half) {
                int row = row0 + half * 8;
                float2 v = make_float2(d[mt][nt][half * 2], d[mt][nt][half * 2 + 1]);
                if (resp) {
                    float mk = mask ? mask[row] : 1.0f;
                    float2 r2 = *(const float2*)&resp[row * nPerW + col];
                    v.x = r2.x + v.x * mk;
                    v.y = r2.y + v.y * mk;
                }
                *(float2*)&outp[row * nPerW + col] = v;
            }
        }
    }
}

// ---------------------------------------------------------------------------
// Per-head plain LN over DH=32 (one warp per (token,head) vector), in place.
__global__ void headln_kernel(int off) {
    int gid = blockIdx.x * 8 + (threadIdx.x >> 5);
    int lane = threadIdx.x & 31;
    int i = gid >> 4, h = gid & 15;
    float* p = g_buf + off + i * DD + h * DH + lane;
    float x = *p;
    float s = x;
#pragma unroll
    for (int o = 16; o; o >>= 1) s += __shfl_xor_sync(0xffffffffu, s, o);
    float m = s * (1.0f / DH);
    float d = x - m;
    float v = d * d;
#pragma unroll
    for (int o = 16; o; o >>= 1) v += __shfl_xor_sync(0xffffffffu, v, o);
    float var = v * (1.0f / DH);
    *p = d * rsqrtf(var + 1e-5f);
}

// ---------------------------------------------------------------------------
// E[h,i,j] = exp( pair_mask ? (QK/sqrt(32)+bias-sigmoid(wdl)*d2/100)/eps_h : -1e9 )
__global__ void logk_kernel(const int* __restrict__ bins, const float* __restrict__ pw,
                            const float* __restrict__ wdl, const float* __restrict__ eps,
                            const float* __restrict__ mask, const float* __restrict__ xr) {
    __shared__ float Qs[32 * 65], Ks[32 * 65];
    __shared__ float xi[64][3], xj[64][3], mi[64], mj[64], pwh[NBINS];
    int h = blockIdx.z, i0 = blockIdx.y * 64, j0 = blockIdx.x * 64;
    int tid = threadIdx.x;
    for (int t = tid; t < 64 * 32; t += 256) {
        int r = t >> 5, k = t & 31;
        Qs[k * 65 + r] = g_buf[OFF_Q + (i0 + r) * DD + h * DH + k];
        Ks[k * 65 + r] = g_buf[OFF_K + (j0 + r) * DD + h * DH + k];
    }
    if (tid < 64) {
        mi[tid] = mask[i0 + tid];
        mj[tid] = mask[j0 + tid];
        xi[tid][0] = xr[(i0 + tid) * 3 + 0];
        xi[tid][1] = xr[(i0 + tid) * 3 + 1];
        xi[tid][2] = xr[(i0 + tid) * 3 + 2];
        xj[tid][0] = xr[(j0 + tid) * 3 + 0];
        xj[tid][1] = xr[(j0 + tid) * 3 + 1];
        xj[tid][2] = xr[(j0 + tid) * 3 + 2];
    }
    if (tid < NBINS) pwh[tid] = pw[tid * HH + h];
    __syncthreads();

    int tx = tid & 15, ty = tid >> 4;
    float acc[4][4];
#pragma unroll
    for (int i = 0; i < 4; ++i)
#pragma unroll
        for (int j = 0; j < 4; ++j) acc[i][j] = 0.0f;
#pragma unroll
    for (int k = 0; k < 32; ++k) {
        float a[4], b[4];
#pragma unroll
        for (int i = 0; i < 4; ++i) a[i] = Qs[k * 65 + ty + 16 * i];
#pragma unroll
        for (int j = 0; j < 4; ++j) b[j] = Ks[k * 65 + tx + 16 * j];
#pragma unroll
        for (int i = 0; i < 4; ++i)
#pragma unroll
            for (int j = 0; j < 4; ++j) acc[i][j] += a[i] * b[j];
    }
    float wd = 1.0f / (1.0f + expf(-wdl[h]));
    float ie = 1.0f / eps[h];
    const float s32 = 0.17677669529663687f;  // 1/sqrt(32)
#pragma unroll
    for (int ii = 0; ii < 4; ++ii) {
        int il = ty + 16 * ii, i = i0 + il;
#pragma unroll
        for (int jj = 0; jj < 4; ++jj) {
            int jl = tx + 16 * jj, j = j0 + jl;
            int bn = bins[i * NN + j];
            float d0 = xi[il][0] - xj[jl][0];
            float d1 = xi[il][1] - xj[jl][1];
            float d2c = xi[il][2] - xj[jl][2];
            float dd = d0 * d0 + d1 * d1 + d2c * d2c;
            float logit = acc[ii][jj] * s32 + pwh[bn] - wd * dd * 0.01f;
            float lk = (mi[il] * mj[jl] > 0.0f) ? logit * ie : -1e9f;
            g_buf[OFF_EK + (h * NN + i) * NN + j] = __expf(lk);
        }
    }
}

// ---------------------------------------------------------------------------
__global__ void skprep_kernel(const float* __restrict__ mu, const float* __restrict__ nu,
                              const float* __restrict__ lup, const float* __restrict__ lvp) {
    int idx = blockIdx.x * 256 + threadIdx.x;
    if (idx >= HH * NN) return;
    g_buf[OFF_LOGMU + idx] = logf(fmaxf(mu[idx], 1e-8f));
    g_buf[OFF_LOGNU + idx] = logf(fmaxf(nu[idx], 1e-8f));
    g_buf[OFF_U + idx] = lup[idx];
    g_buf[OFF_V2 + idx] = lvp[idx];
}

// log_u[h,i] = fi*(log_mu - log(sum_j E[h,i,j]*exp(log_v[h,j])))
// One warp per row; pure FMA matvec over L2-resident E.
__global__ void __launch_bounds__(256) sk_u_kernel(const float* __restrict__ eps) {
    __shared__ float sv[NN];
    int h = blockIdx.y;
    for (int t = threadIdx.x; t < NN; t += 256) sv[t] = __expf(g_buf[OFF_V2 + h * NN + t]);
    __syncthreads();
    int w = threadIdx.x >> 5, lane = threadIdx.x & 31;
    int i = blockIdx.x * 8 + w;
    const float4* row = (const float4*)(g_buf + OFF_EK + (h * NN + i) * NN);
    const float4* svv = (const float4*)sv;
    float s = 0.0f;
#pragma unroll
    for (int q = 0; q < 8; ++q) {
        float4 a = row[q * 32 + lane];
        float4 b = svv[q * 32 + lane];
        s += a.x * b.x + a.y * b.y + a.z * b.z + a.w * b.w;
    }
#pragma unroll
    for (int o = 16; o; o >>= 1) s += __shfl_xor_sync(0xffffffffu, s, o);
    if (lane == 0) {
        float fi = 1.0f / (1.0f + eps[h]);
        g_buf[OFF_U + h * NN + i] = fi * (g_buf[OFF_LOGMU + h * NN + i] - logf(s));
    }
}

// log_v[h,j] = fi*(log_nu - log(sum_i E[h,i,j]*exp(log_u[h,i])))
__global__ void sk_v_kernel(const float* __restrict__ eps) {
    __shared__ float su[NN];
    __shared__ float rsum[8][33];
    int h = blockIdx.y;
    for (int t = threadIdx.x; t < NN; t += 256) su[t] = __expf(g_buf[OFF_U + h * NN + t]);
    __syncthreads();
    int jx = threadIdx.x & 31, sy = threadIdx.x >> 5;
    int j = blockIdx.x * 32 + jx;
    const float* col = g_buf + OFF_EK + h * NN * NN + j;
    float s = 0.0f;
    int i0 = sy * 128;
#pragma unroll 4
    for (int t = 0; t < 128; ++t) {
        int i = i0 + t;
        s += col[i * NN] * su[i];
    }
    rsum[sy][jx] = s;
    __syncthreads();
    if (sy == 0) {
        float S = s;
#pragma unroll
        for (int k = 1; k < 8; ++k) S += rsum[k][jx];
        float fi = 1.0f / (1.0f + eps[h]);
        g_buf[OFF_V2 + h * NN + j] = fi * (g_buf[OFF_LOGNU + h * NN + j] - logf(S));
    }
}

// ---------------------------------------------------------------------------
// Pack Vx[h][j][c]: c<32 -> V head slice, c=32..34 -> x_res
__global__ void pack_kernel(const float* __restrict__ xr) {
    int idx = blockIdx.x * 256 + threadIdx.x;
    if (idx >= HH * NN * 35) return;
    int c = idx % 35;
    int hj = idx / 35;
    int j = hj & (NN - 1);
    int h = hj >> 10;
    float v = (c < 32) ? g_buf[OFF_V + j * DD + h * DH + c] : xr[j * 3 + (c - 32)];
    g_buf[OFF_VXP + idx] = v;
}

// Fused: P = E*eu*ev, rowsum clip, attn = Pn@V * sigmoid(G), x_cent = Pn@x_res.
// 1024 blocks = 16 heads x 64 row-blocks of 16 rows. Warp handles 2 rows.
__global__ void __launch_bounds__(256, 2) attn_kernel() {
    __shared__ float sVx[256 * 36];
    __shared__ float sv[256];
    int h = blockIdx.x >> 6;
    int w = threadIdx.x >> 5, lane = threadIdx.x & 31;
    int i0 = (blockIdx.x & 63) * 16 + w * 2;
    float eu0 = __expf(g_buf[OFF_U + h * NN + i0 + 0]);
    float eu1 = __expf(g_buf[OFF_U + h * NN + i0 + 1]);
    const float* lk0 = g_buf + OFF_EK + (h * NN + i0) * NN;

    for (int t = threadIdx.x; t < 256; t += 256) sVx[t * 36 + 35] = 0.0f;

    float acc[2][36];
#pragma unroll
    for (int r = 0; r < 2; ++r)
#pragma unroll
        for (int c = 0; c < 36; ++c) acc[r][c] = 0.0f;
    float rs0 = 0.f, rs1 = 0.f;

    for (int cb = 0; cb < 4; ++cb) {
        int jb = cb * 256;
        __syncthreads();
        const float* src = g_buf + OFF_VXP + (h * NN + jb) * 35;
        for (int t = threadIdx.x; t < 256 * 35; t += 256) {
            int jo = t / 35, c = t - jo * 35;
            sVx[jo * 36 + c] = src[t];
        }
        sv[threadIdx.x] = __expf(g_buf[OFF_V2 + h * NN + jb + threadIdx.x]);
        __syncthreads();
#pragma unroll 1
        for (int s = 0; s < 8; ++s) {
            int jl = s * 32 + lane;
            int j = jb + jl;
            float vj = sv[jl];
            float p0 = lk0[j] * vj;
            float p1 = lk0[NN + j] * vj;
            rs0 += p0; rs1 += p1;
            const float4* vp = (const float4*)(sVx + jl * 36);
#pragma unroll
            for (int c4 = 0; c4 < 9; ++c4) {
                float4 vv = vp[c4];
                acc[0][c4 * 4 + 0] += p0 * vv.x; acc[0][c4 * 4 + 1] += p0 * vv.y;
                acc[0][c4 * 4 + 2] += p0 * vv.z; acc[0][c4 * 4 + 3] += p0 * vv.w;
                acc[1][c4 * 4 + 0] += p1 * vv.x; acc[1][c4 * 4 + 1] += p1 * vv.y;
                acc[1][c4 * 4 + 2] += p1 * vv.z; acc[1][c4 * 4 + 3] += p1 * vv.w;
            }
        }
    }

    // Pn_ij = (E_ij*ev_j*eu_i) / max(eu_i*rs_i, 1e-8)
    float rsv[2] = {rs0, rs1};
    float euv[2] = {eu0, eu1};
#pragma unroll
    for (int r = 0; r < 2; ++r) {
        float t = rsv[r];
#pragma unroll
        for (int o = 16; o; o >>= 1) t += __shfl_xor_sync(0xffffffffu, t, o);
        rsv[r] = t;
    }
#pragma unroll
    for (int r = 0; r < 2; ++r) {
        int i = i0 + r;
        float inv = euv[r] / fmaxf(euv[r] * rsv[r], 1e-8f);
#pragma unroll
        for (int c = 0; c < 35; ++c) {
            float a = acc[r][c];
#pragma unroll
            for (int o = 16; o; o >>= 1) a += __shfl_xor_sync(0xffffffffu, a, o);
            if (c < 32) {
                if (lane == c) {
                    float g = g_buf[OFF_G + i * DD + h * DH + c];
                    float sg = 1.0f / (1.0f + __expf(-g));
                    g_buf[OFF_ATTN + i * DD + h * DH + c] = a * inv * sg;
                }
            } else {
                if (lane == c - 32) {
                    g_buf[OFF_XC + (h * NN + i) * 3 + (c - 32)] = a * inv;
                }
            }
        }
    }
}

// ---------------------------------------------------------------------------
__global__ void xupd_kernel(const float* __restrict__ xr, const float* __restrict__ mask,
                            const float* __restrict__ gamma, float* __restrict__ out) {
    int i = blockIdx.x * 256 + threadIdx.x;
    if (i >= NN) return;
    float x0 = xr[i * 3 + 0], x1 = xr[i * 3 + 1], x2 = xr[i * 3 + 2];
    float a0 = 0.f, a1 = 0.f, a2 = 0.f;
#pragma unroll
    for (int h = 0; h < HH; ++h) {
        float th = tanhf(gamma[h]) * (1.0f / HH);
        const float* xc = g_buf + OFF_XC + (h * NN + i) * 3;
        a0 += th * (x0 - xc[0]);
        a1 += th * (x1 - xc[1]);
        a2 += th * (x2 - xc[2]);
    }
    float mk = mask[i];
    out[i * 3 + 0] = x0 + a0 * mk;
    out[i * 3 + 1] = x1 + a1 * mk;
    out[i * 3 + 2] = x2 + a2 * mk;
}

__global__ void copyuv_kernel(float* __restrict__ out) {
    int idx = blockIdx.x * 256 + threadIdx.x;
    if (idx >= HH * NN) return;
    out[OUT_U + idx] = g_buf[OFF_U + idx];
    out[OUT_V + idx] = g_buf[OFF_V2 + idx];
}

__global__ void silu_kernel() {
    int idx = blockIdx.x * 256 + threadIdx.x;
    if (idx >= NN * 4 * DD) return;
    float a = g_buf[OFF_FFA + idx];
    float b = g_buf[OFF_FFB + idx];
    g_buf[OFF_FFG + idx] = a * b / (1.0f + __expf(-a));
}

// ---------------------------------------------------------------------------
extern "C" void kernel_launch(void* const* d_in, const int* in_sizes, int n_in,
                              void* d_out, int out_size) {
    const float* h    = (const float*)d_in[0];
    const float* xres = (const float*)d_in[1];
    const float* mu   = (const float*)d_in[2];
    const float* nu   = (const float*)d_in[3];
    const float* lup  = (const float*)d_in[4];
    const float* lvp  = (const float*)d_in[5];
    const float* mask = (const float*)d_in[6];
    const float* lnw  = (const float*)d_in[7];
    const float* lnb  = (const float*)d_in[8];
    const float* wq   = (const float*)d_in[9];
    const float* wk   = (const float*)d_in[10];
    const float* wv   = (const float*)d_in[11];
    const float* wg   = (const float*)d_in[12];
    const float* wo   = (const float*)d_in[13];
    const float* gamma= (const float*)d_in[14];
    const float* pw   = (const float*)d_in[15];
    const float* wdl  = (const float*)d_in[16];
    const float* lnfw = (const float*)d_in[17];
    const float* lnfb = (const float*)d_in[18];
    const float* w1   = (const float*)d_in[19];
    const float* w3   = (const float*)d_in[20];
    const float* w2   = (const float*)d_in[21];
    const int*   bins = (const int*)d_in[22];
    const float* eps  = (const float*)d_in[23];
    float* out = (float*)d_out;

    // 1. pre-LN
    ln_kernel<<<NN, 256>>>(h, 0, lnw, lnb, OFF_HN);

    // 2. fused Q|K|V|G projection: N=2048, segments land at OFF_Q..OFF_G
    tgemm_kernel<128, 128><<<dim3(16, 8), 256>>>(OFF_HN, wq, wk, wv, wg, DD,
                                                 OFF_Q, 0, 0, -1, 0, NN, DD);

    // 3. per-head plain LN on Q, K
    headln_kernel<<<2048, 256>>>(OFF_Q);
    headln_kernel<<<2048, 256>>>(OFF_K);

    // 4. E = exp(logK)
    logk_kernel<<<dim3(16, 16, 16), 256>>>(bins, pw, wdl, eps, mask, xres);

    // 5. Sinkhorn (multiplicative-domain passes over E, log-domain u/v state)
    skprep_kernel<<<64, 256>>>(mu, nu, lup, lvp);
    for (int it = 0; it < 20; ++it) {
        sk_u_kernel<<<dim3(128, 16), 256>>>(eps);
        sk_v_kernel<<<dim3(32, 16), 256>>>(eps);
    }
    copyuv_kernel<<<64, 256>>>(out);

    // 6. fused transport-plan attention + centroids
    pack_kernel<<<(HH * NN * 35 + 255) / 256, 256>>>(xres);
    attn_kernel<<<1024, 256>>>();
    xupd_kernel<<<4, 256>>>(xres, mask, gamma, out + OUT_X);

    // 7. output projection + residual
    tgemm_kernel<64, 64><<<dim3(8, 16), 256>>>(OFF_ATTN, wo, wo, wo, wo, DD,
                                               OFF_HMID, 0, h, -1, mask, NN, DD);

    // 8. FFN
    ln_kernel<<<NN, 256>>>(0, OFF_HMID, lnfw, lnfb, OFF_H2);
    tgemm_kernel<128, 128><<<dim3(32, 8), 256>>>(OFF_H2, w1, w3, w1, w1, 4 * DD,
                                                 OFF_FFA, 0, 0, -1, 0, NN, DD);
    silu_kernel<<<(NN * 4 * DD + 255) / 256, 256>>>();
    tgemm_kernel<64, 64><<<dim3(8, 16), 256>>>(OFF_FFG, w2, w2, w2, w2, DD,
                                               0, out + OUT_H, 0, OFF_HMID, mask, NN, 4 * DD);
}

// round 8
// speedup vs baseline: 2.2378x; 1.0355x over previous
#include <cuda_runtime.h>
#include <cuda_fp16.h>
#include <math.h>
#include <stdint.h>

#define NN 1024
#define DD 512
#define HH 16
#define DH 32
#define NBINS 68

// ---- scratch layout (float offsets into one big __device__ buffer) ----
#define OFF_HN     0
#define OFF_Q      524288
#define OFF_K      1048576
#define OFF_V      1572864
#define OFF_G      2097152
#define OFF_EK     2621440          /* E = exp(logK) as fp16: 16M halves = 8M floats */
#define OFF_LOGMU  19398656
#define OFF_LOGNU  19415040
#define OFF_U      19431424
#define OFF_V2     19447808
#define OFF_VXP    19464192
#define OFF_ATTN   20037632
#define OFF_XC     20561920
#define OFF_HMID   20611072
#define OFF_H2     21135360
#define OFF_FFA    21659648
#define OFF_FFB    23756800
#define OFF_FFG    25853952
#define BUF_TOTAL  27951104

__device__ float g_buf[BUF_TOTAL];

// Output layout: [h | x_res | log_u | log_v]
#define OUT_H 0
#define OUT_X 524288
#define OUT_U 527360
#define OUT_V 543744

// ---------------------------------------------------------------------------
__device__ __forceinline__ float tf32r(float x) {
    uint32_t u;
    asm("cvt.rna.tf32.f32 %0, %1;" : "=r"(u) : "f"(x));
    return __uint_as_float(u);
}

__device__ __forceinline__ void mma_tf32(float* d, const uint32_t* a, const uint32_t* b) {
    asm volatile(
        "mma.sync.aligned.m16n8k8.row.col.f32.tf32.tf32.f32 "
        "{%0,%1,%2,%3}, {%4,%5,%6,%7}, {%8,%9}, {%0,%1,%2,%3};"
        : "+f"(d[0]), "+f"(d[1]), "+f"(d[2]), "+f"(d[3])
        : "r"(a[0]), "r"(a[1]), "r"(a[2]), "r"(a[3]), "r"(b[0]), "r"(b[1]));
}

// ---------------------------------------------------------------------------
// LayerNorm over last dim D=512. One block per row, 256 threads.
__global__ void ln_kernel(const float* __restrict__ inExt, int inOff,
                          const float* __restrict__ w, const float* __restrict__ b,
                          int outOff) {
    const float* in = inExt ? inExt : (g_buf + inOff);
    int row = blockIdx.x, tid = threadIdx.x;
    __shared__ float red[256];
    float x0 = in[row * DD + tid];
    float x1 = in[row * DD + 256 + tid];
    red[tid] = x0 + x1;
    __syncthreads();
    for (int o = 128; o; o >>= 1) { if (tid < o) red[tid] += red[tid + o]; __syncthreads(); }
    float m = red[0] * (1.0f / DD);
    __syncthreads();
    float d0 = x0 - m, d1 = x1 - m;
    red[tid] = d0 * d0 + d1 * d1;
    __syncthreads();
    for (int o = 128; o; o >>= 1) { if (tid < o) red[tid] += red[tid + o]; __syncthreads(); }
    float var = red[0] * (1.0f / DD);
    float rs = rsqrtf(var + 1e-5f);
    float* out = g_buf + outOff;
    out[row * DD + tid]       = d0 * rs * w[tid]       + b[tid];
    out[row * DD + 256 + tid] = d1 * rs * w[tid + 256] + b[tid + 256];
}

// ---------------------------------------------------------------------------
// TF32 tensor-core GEMM: C[M,N] = A[M,K] @ B[N,K]^T, up to 4 weight matrices
// as consecutive nPerW-wide output segments. Optional epilogue
// out = res + C*mask[row]. 256 threads = 8 warps (2 x 4), warp tile (BM/2 x BN/4).
template<int BM, int BN>
__global__ void __launch_bounds__(256) tgemm_kernel(
    int aOff, const float* __restrict__ B0, const float* __restrict__ B1,
    const float* __restrict__ B2, const float* __restrict__ B3,
    int nPerW, int cOff, float* __restrict__ outExt,
    const float* __restrict__ resExt, int resOff,
    const float* __restrict__ mask, int M, int K) {
    constexpr int BK = 16;
    constexpr int WM = BM / 2, WN = BN / 4;
    constexpr int MT = WM / 16, NT = WN / 8;
    __shared__ float As[BM][BK + 4];
    __shared__ float Bs[BN][BK + 4];
    const float* A = g_buf + aOff;
    int m0 = blockIdx.y * BM, n0 = blockIdx.x * BN;
    int widx = n0 / nPerW;
    const float* Bw = (widx == 0) ? B0 : (widx == 1) ? B1 : (widx == 2) ? B2 : B3;
    int nloc0 = n0 - widx * nPerW;

    int tid = threadIdx.x, lane = tid & 31, wid = tid >> 5;
    int warpM = wid >> 2, warpN = wid & 3;

    float d[MT][NT][4];
#pragma unroll
    for (int mt = 0; mt < MT; ++mt)
#pragma unroll
        for (int nt = 0; nt < NT; ++nt)
#pragma unroll
            for (int q = 0; q < 4; ++q) d[mt][nt][q] = 0.0f;

    for (int k0 = 0; k0 < K; k0 += BK) {
#pragma unroll
        for (int t0 = 0; t0 < BM * 4; t0 += 256) {
            int t = t0 + tid;
            int r = t >> 2, kq = (t & 3) << 2;
            float4 v = *(const float4*)&A[(m0 + r) * K + k0 + kq];
            float4 c = make_float4(tf32r(v.x), tf32r(v.y), tf32r(v.z), tf32r(v.w));
            *(float4*)&As[r][kq] = c;
        }
#pragma unroll
        for (int t0 = 0; t0 < BN * 4; t0 += 256) {
            int t = t0 + tid;
            int r = t >> 2, kq = (t & 3) << 2;
            float4 v = *(const float4*)&Bw[(nloc0 + r) * K + k0 + kq];
            float4 c = make_float4(tf32r(v.x), tf32r(v.y), tf32r(v.z), tf32r(v.w));
            *(float4*)&Bs[r][kq] = c;
        }
        __syncthreads();
#pragma unroll
        for (int ks = 0; ks < 2; ++ks) {
            int kb = ks * 8;
            uint32_t a[MT][4], b[NT][2];
#pragma unroll
            for (int mt = 0; mt < MT; ++mt) {
                int r = warpM * WM + mt * 16 + (lane >> 2);
                int c = kb + (lane & 3);
                a[mt][0] = __float_as_uint(As[r][c]);
                a[mt][1] = __float_as_uint(As[r + 8][c]);
                a[mt][2] = __float_as_uint(As[r][c + 4]);
                a[mt][3] = __float_as_uint(As[r + 8][c + 4]);
            }
#pragma unroll
            for (int nt = 0; nt < NT; ++nt) {
                int r = warpN * WN + nt * 8 + (lane >> 2);
                int c = kb + (lane & 3);
                b[nt][0] = __float_as_uint(Bs[r][c]);
                b[nt][1] = __float_as_uint(Bs[r][c + 4]);
            }
#pragma unroll
            for (int mt = 0; mt < MT; ++mt)
#pragma unroll
                for (int nt = 0; nt < NT; ++nt) mma_tf32(d[mt][nt], a[mt], b[nt]);
        }
        __syncthreads();
    }

    float* outp = (outExt ? outExt : (g_buf + cOff)) + (long)widx * M * nPerW;
    const float* resp = resExt ? resExt : (resOff >= 0 ? (g_buf + resOff) : (const float*)0);
#pragma unroll
    for (int mt = 0; mt < MT; ++mt) {
        int row0 = m0 + warpM * WM + mt * 16 + (lane >> 2);
#pragma unroll
        for (int nt = 0; nt < NT; ++nt) {
            int col = nloc0 + warpN * WN + nt * 8 + (lane & 3) * 2;
#pragma unroll
            for (int half = 0; half < 2; ++half) {
                int row = row0 + half * 8;
                float2 v = make_float2(d[mt][nt][half * 2], d[mt][nt][half * 2 + 1]);
                if (resp) {
                    float mk = mask ? mask[row] : 1.0f;
                    float2 r2 = *(const float2*)&resp[row * nPerW + col];
                    v.x = r2.x + v.x * mk;
                    v.y = r2.y + v.y * mk;
                }
                *(float2*)&outp[row * nPerW + col] = v;
            }
        }
    }
}

// ---------------------------------------------------------------------------
// Per-head plain LN over DH=32 (one warp per (token,head) vector), in place.
__global__ void headln_kernel(int off) {
    int gid = blockIdx.x * 8 + (threadIdx.x >> 5);
    int lane = threadIdx.x & 31;
    int i = gid >> 4, h = gid & 15;
    float* p = g_buf + off + i * DD + h * DH + lane;
    float x = *p;
    float s = x;
#pragma unroll
    for (int o = 16; o; o >>= 1) s += __shfl_xor_sync(0xffffffffu, s, o);
    float m = s * (1.0f / DH);
    float d = x - m;
    float v = d * d;
#pragma unroll
    for (int o = 16; o; o >>= 1) v += __shfl_xor_sync(0xffffffffu, v, o);
    float var = v * (1.0f / DH);
    *p = d * rsqrtf(var + 1e-5f);
}

// ---------------------------------------------------------------------------
// E[h,i,j] = exp( pair_mask ? (QK/sqrt(32)+bias-sigmoid(wdl)*d2/100)/eps_h : -1e9 )  [fp16]
__global__ void logk_kernel(const int* __restrict__ bins, const float* __restrict__ pw,
                            const float* __restrict__ wdl, const float* __restrict__ eps,
                            const float* __restrict__ mask, const float* __restrict__ xr) {
    __shared__ float Qs[32 * 65], Ks[32 * 65];
    __shared__ float xi[64][3], xj[64][3], mi[64], mj[64], pwh[NBINS];
    __half* EK = (__half*)(g_buf + OFF_EK);
    int h = blockIdx.z, i0 = blockIdx.y * 64, j0 = blockIdx.x * 64;
    int tid = threadIdx.x;
    for (int t = tid; t < 64 * 32; t += 256) {
        int r = t >> 5, k = t & 31;
        Qs[k * 65 + r] = g_buf[OFF_Q + (i0 + r) * DD + h * DH + k];
        Ks[k * 65 + r] = g_buf[OFF_K + (j0 + r) * DD + h * DH + k];
    }
    if (tid < 64) {
        mi[tid] = mask[i0 + tid];
        mj[tid] = mask[j0 + tid];
        xi[tid][0] = xr[(i0 + tid) * 3 + 0];
        xi[tid][1] = xr[(i0 + tid) * 3 + 1];
        xi[tid][2] = xr[(i0 + tid) * 3 + 2];
        xj[tid][0] = xr[(j0 + tid) * 3 + 0];
        xj[tid][1] = xr[(j0 + tid) * 3 + 1];
        xj[tid][2] = xr[(j0 + tid) * 3 + 2];
    }
    if (tid < NBINS) pwh[tid] = pw[tid * HH + h];
    __syncthreads();

    int tx = tid & 15, ty = tid >> 4;
    float acc[4][4];
#pragma unroll
    for (int i = 0; i < 4; ++i)
#pragma unroll
        for (int j = 0; j < 4; ++j) acc[i][j] = 0.0f;
#pragma unroll
    for (int k = 0; k < 32; ++k) {
        float a[4], b[4];
#pragma unroll
        for (int i = 0; i < 4; ++i) a[i] = Qs[k * 65 + ty + 16 * i];
#pragma unroll
        for (int j = 0; j < 4; ++j) b[j] = Ks[k * 65 + tx + 16 * j];
#pragma unroll
        for (int i = 0; i < 4; ++i)
#pragma unroll
            for (int j = 0; j < 4; ++j) acc[i][j] += a[i] * b[j];
    }
    float wd = 1.0f / (1.0f + expf(-wdl[h]));
    float ie = 1.0f / eps[h];
    const float s32 = 0.17677669529663687f;  // 1/sqrt(32)
#pragma unroll
    for (int ii = 0; ii < 4; ++ii) {
        int il = ty + 16 * ii, i = i0 + il;
#pragma unroll
        for (int jj = 0; jj < 4; ++jj) {
            int jl = tx + 16 * jj, j = j0 + jl;
            int bn = bins[i * NN + j];
            float d0 = xi[il][0] - xj[jl][0];
            float d1 = xi[il][1] - xj[jl][1];
            float d2c = xi[il][2] - xj[jl][2];
            float dd = d0 * d0 + d1 * d1 + d2c * d2c;
            float logit = acc[ii][jj] * s32 + pwh[bn] - wd * dd * 0.01f;
            float lk = (mi[il] * mj[jl] > 0.0f) ? logit * ie : -1e9f;
            EK[(h * NN + i) * NN + j] = __float2half(__expf(lk));
        }
    }
}

// ---------------------------------------------------------------------------
__global__ void skprep_kernel(const float* __restrict__ mu, const float* __restrict__ nu,
                              const float* __restrict__ lup, const float* __restrict__ lvp) {
    int idx = blockIdx.x * 256 + threadIdx.x;
    if (idx >= HH * NN) return;
    g_buf[OFF_LOGMU + idx] = logf(fmaxf(mu[idx], 1e-8f));
    g_buf[OFF_LOGNU + idx] = logf(fmaxf(nu[idx], 1e-8f));
    g_buf[OFF_U + idx] = lup[idx];
    g_buf[OFF_V2 + idx] = lvp[idx];
}

// log_u[h,i] = fi*(log_mu - log(sum_j E[h,i,j]*exp(log_v[h,j])))
// One warp per row; fp16 E rows loaded as uint4 (8 halves).
__global__ void __launch_bounds__(256) sk_u_kernel(const float* __restrict__ eps) {
    __shared__ float sv[NN];
    int h = blockIdx.y;
    for (int t = threadIdx.x; t < NN; t += 256) sv[t] = __expf(g_buf[OFF_V2 + h * NN + t]);
    __syncthreads();
    const __half* EK = (const __half*)(g_buf + OFF_EK);
    int w = threadIdx.x >> 5, lane = threadIdx.x & 31;
    int i = blockIdx.x * 8 + w;
    const uint4* row = (const uint4*)(EK + (h * NN + i) * NN);
    float s = 0.0f;
#pragma unroll
    for (int q = 0; q < 4; ++q) {
        uint4 pk = row[q * 32 + lane];
        int jb = (q * 32 + lane) * 8;
        float2 e0 = __half22float2(*(const __half2*)&pk.x);
        float2 e1 = __half22float2(*(const __half2*)&pk.y);
        float2 e2 = __half22float2(*(const __half2*)&pk.z);
        float2 e3 = __half22float2(*(const __half2*)&pk.w);
        float4 s0 = *(const float4*)&sv[jb];
        float4 s1 = *(const float4*)&sv[jb + 4];
        s += e0.x * s0.x + e0.y * s0.y + e1.x * s0.z + e1.y * s0.w;
        s += e2.x * s1.x + e2.y * s1.y + e3.x * s1.z + e3.y * s1.w;
    }
#pragma unroll
    for (int o = 16; o; o >>= 1) s += __shfl_xor_sync(0xffffffffu, s, o);
    if (lane == 0) {
        float fi = 1.0f / (1.0f + eps[h]);
        g_buf[OFF_U + h * NN + i] = fi * (g_buf[OFF_LOGMU + h * NN + i] - logf(s));
    }
}

// log_v[h,j] = fi*(log_nu - log(sum_i E[h,i,j]*exp(log_u[h,i])))
// Block: 64 j's (half2 per lane), 8 warps split the i range; smem combine.
__global__ void __launch_bounds__(256) sk_v_kernel(const float* __restrict__ eps) {
    __shared__ float su[NN];
    __shared__ float rsum[8][66];
    int h = blockIdx.y;
    for (int t = threadIdx.x; t < NN; t += 256) su[t] = __expf(g_buf[OFF_U + h * NN + t]);
    __syncthreads();
    const __half* EK = (const __half*)(g_buf + OFF_EK);
    int lane = threadIdx.x & 31, w = threadIdx.x >> 5;
    int jb = blockIdx.x * 64;
    const __half2* col = (const __half2*)(EK + h * NN * NN + jb) + lane;
    float s0 = 0.0f, s1 = 0.0f;
    int i0 = w * 128;
#pragma unroll 4
    for (int t = 0; t < 128; ++t) {
        int i = i0 + t;
        float2 e = __half22float2(col[i * (NN / 2)]);
        float uu = su[i];
        s0 += e.x * uu;
        s1 += e.y * uu;
    }
    rsum[w][lane * 2] = s0;
    rsum[w][lane * 2 + 1] = s1;
    __syncthreads();
    if (threadIdx.x < 64) {
        int jx = threadIdx.x;
        float S = rsum[0][jx];
#pragma unroll
        for (int k = 1; k < 8; ++k) S += rsum[k][jx];
        float fi = 1.0f / (1.0f + eps[h]);
        g_buf[OFF_V2 + h * NN + jb + jx] = fi * (g_buf[OFF_LOGNU + h * NN + jb + jx] - logf(S));
    }
}

// ---------------------------------------------------------------------------
// Pack Vx[h][j][c]: c<32 -> V head slice, c=32..34 -> x_res
__global__ void pack_kernel(const float* __restrict__ xr) {
    int idx = blockIdx.x * 256 + threadIdx.x;
    if (idx >= HH * NN * 35) return;
    int c = idx % 35;
    int hj = idx / 35;
    int j = hj & (NN - 1);
    int h = hj >> 10;
    float v = (c < 32) ? g_buf[OFF_V + j * DD + h * DH + c] : xr[j * 3 + (c - 32)];
    g_buf[OFF_VXP + idx] = v;
}

// Fused: P = E*eu*ev, rowsum clip, attn = Pn@V * sigmoid(G), x_cent = Pn@x_res.
// 1024 blocks = 16 heads x 64 row-blocks of 16 rows. Warp handles 2 rows.
__global__ void __launch_bounds__(256, 2) attn_kernel() {
    __shared__ float sVx[256 * 36];
    __shared__ float sv[256];
    const __half* EK = (const __half*)(g_buf + OFF_EK);
    int h = blockIdx.x >> 6;
    int w = threadIdx.x >> 5, lane = threadIdx.x & 31;
    int i0 = (blockIdx.x & 63) * 16 + w * 2;
    float eu0 = __expf(g_buf[OFF_U + h * NN + i0 + 0]);
    float eu1 = __expf(g_buf[OFF_U + h * NN + i0 + 1]);
    const __half* lk0 = EK + (h * NN + i0) * NN;

    float acc[2][36];
#pragma unroll
    for (int r = 0; r < 2; ++r)
#pragma unroll
        for (int c = 0; c < 36; ++c) acc[r][c] = 0.0f;
    float rs0 = 0.f, rs1 = 0.f;

    for (int cb = 0; cb < 4; ++cb) {
        int jb = cb * 256;
        __syncthreads();
        const float* src = g_buf + OFF_VXP + (h * NN + jb) * 35;
        for (int t = threadIdx.x; t < 256 * 35; t += 256) {
            int jo = t / 35, c = t - jo * 35;
            sVx[jo * 36 + c] = src[t];
        }
        sv[threadIdx.x] = __expf(g_buf[OFF_V2 + h * NN + jb + threadIdx.x]);
        __syncthreads();
#pragma unroll 1
        for (int s = 0; s < 8; ++s) {
            int jl = s * 32 + lane;
            int j = jb + jl;
            float vj = sv[jl];
            float p0 = __half2float(lk0[j]) * vj;
            float p1 = __half2float(lk0[NN + j]) * vj;
            rs0 += p0; rs1 += p1;
            const float4* vp = (const float4*)(sVx + jl * 36);
#pragma unroll
            for (int c4 = 0; c4 < 9; ++c4) {
                float4 vv = vp[c4];
                acc[0][c4 * 4 + 0] += p0 * vv.x; acc[0][c4 * 4 + 1] += p0 * vv.y;
                acc[0][c4 * 4 + 2] += p0 * vv.z; acc[0][c4 * 4 + 3] += p0 * vv.w;
                acc[1][c4 * 4 + 0] += p1 * vv.x; acc[1][c4 * 4 + 1] += p1 * vv.y;
                acc[1][c4 * 4 + 2] += p1 * vv.z; acc[1][c4 * 4 + 3] += p1 * vv.w;
            }
        }
    }

    // Pn_ij = (E_ij*ev_j*eu_i) / max(eu_i*rs_i, 1e-8)
    float rsv[2] = {rs0, rs1};
    float euv[2] = {eu0, eu1};
#pragma unroll
    for (int r = 0; r < 2; ++r) {
        float t = rsv[r];
#pragma unroll
        for (int o = 16; o; o >>= 1) t += __shfl_xor_sync(0xffffffffu, t, o);
        rsv[r] = t;
    }
#pragma unroll
    for (int r = 0; r < 2; ++r) {
        int i = i0 + r;
        float inv = euv[r] / fmaxf(euv[r] * rsv[r], 1e-8f);
#pragma unroll
        for (int c = 0; c < 35; ++c) {
            float a = acc[r][c];
#pragma unroll
            for (int o = 16; o; o >>= 1) a += __shfl_xor_sync(0xffffffffu, a, o);
            if (c < 32) {
                if (lane == c) {
                    float g = g_buf[OFF_G + i * DD + h * DH + c];
                    float sg = 1.0f / (1.0f + __expf(-g));
                    g_buf[OFF_ATTN + i * DD + h * DH + c] = a * inv * sg;
                }
            } else {
                if (lane == c - 32) {
                    g_buf[OFF_XC + (h * NN + i) * 3 + (c - 32)] = a * inv;
                }
            }
        }
    }
}

// ---------------------------------------------------------------------------
__global__ void xupd_kernel(const float* __restrict__ xr, const float* __restrict__ mask,
                            const float* __restrict__ gamma, float* __restrict__ out) {
    int i = blockIdx.x * 256 + threadIdx.x;
    if (i >= NN) return;
    float x0 = xr[i * 3 + 0], x1 = xr[i * 3 + 1], x2 = xr[i * 3 + 2];
    float a0 = 0.f, a1 = 0.f, a2 = 0.f;
#pragma unroll
    for (int h = 0; h < HH; ++h) {
        float th = tanhf(gamma[h]) * (1.0f / HH);
        const float* xc = g_buf + OFF_XC + (h * NN + i) * 3;
        a0 += th * (x0 - xc[0]);
        a1 += th * (x1 - xc[1]);
        a2 += th * (x2 - xc[2]);
    }
    float mk = mask[i];
    out[i * 3 + 0] = x0 + a0 * mk;
    out[i * 3 + 1] = x1 + a1 * mk;
    out[i * 3 + 2] = x2 + a2 * mk;
}

__global__ void copyuv_kernel(float* __restrict__ out) {
    int idx = blockIdx.x * 256 + threadIdx.x;
    if (idx >= HH * NN) return;
    out[OUT_U + idx] = g_buf[OFF_U + idx];
    out[OUT_V + idx] = g_buf[OFF_V2 + idx];
}

__global__ void silu_kernel() {
    int idx = blockIdx.x * 256 + threadIdx.x;
    if (idx >= NN * 4 * DD) return;
    float a = g_buf[OFF_FFA + idx];
    float b = g_buf[OFF_FFB + idx];
    g_buf[OFF_FFG + idx] = a * b / (1.0f + __expf(-a));
}

// ---------------------------------------------------------------------------
extern "C" void kernel_launch(void* const* d_in, const int* in_sizes, int n_in,
                              void* d_out, int out_size) {
    const float* h    = (const float*)d_in[0];
    const float* xres = (const float*)d_in[1];
    const float* mu   = (const float*)d_in[2];
    const float* nu   = (const float*)d_in[3];
    const float* lup  = (const float*)d_in[4];
    const float* lvp  = (const float*)d_in[5];
    const float* mask = (const float*)d_in[6];
    const float* lnw  = (const float*)d_in[7];
    const float* lnb  = (const float*)d_in[8];
    const float* wq   = (const float*)d_in[9];
    const float* wk   = (const float*)d_in[10];
    const float* wv   = (const float*)d_in[11];
    const float* wg   = (const float*)d_in[12];
    const float* wo   = (const float*)d_in[13];
    const float* gamma= (const float*)d_in[14];
    const float* pw   = (const float*)d_in[15];
    const float* wdl  = (const float*)d_in[16];
    const float* lnfw = (const float*)d_in[17];
    const float* lnfb = (const float*)d_in[18];
    const float* w1   = (const float*)d_in[19];
    const float* w3   = (const float*)d_in[20];
    const float* w2   = (const float*)d_in[21];
    const int*   bins = (const int*)d_in[22];
    const float* eps  = (const float*)d_in[23];
    float* out = (float*)d_out;

    // 1. pre-LN
    ln_kernel<<<NN, 256>>>(h, 0, lnw, lnb, OFF_HN);

    // 2. fused Q|K|V|G projection: N=2048, segments land at OFF_Q..OFF_G
    tgemm_kernel<128, 128><<<dim3(16, 8), 256>>>(OFF_HN, wq, wk, wv, wg, DD,
                                                 OFF_Q, 0, 0, -1, 0, NN, DD);

    // 3. per-head plain LN on Q, K
    headln_kernel<<<2048, 256>>>(OFF_Q);
    headln_kernel<<<2048, 256>>>(OFF_K);

    // 4. E = exp(logK)  [fp16]
    logk_kernel<<<dim3(16, 16, 16), 256>>>(bins, pw, wdl, eps, mask, xres);

    // 5. Sinkhorn (multiplicative-domain passes over fp16 E, log-domain u/v)
    skprep_kernel<<<64, 256>>>(mu, nu, lup, lvp);
    for (int it = 0; it < 20; ++it) {
        sk_u_kernel<<<dim3(128, 16), 256>>>(eps);
        sk_v_kernel<<<dim3(16, 16), 256>>>(eps);
    }
    copyuv_kernel<<<64, 256>>>(out);

    // 6. fused transport-plan attention + centroids
    pack_kernel<<<(HH * NN * 35 + 255) / 256, 256>>>(xres);
    attn_kernel<<<1024, 256>>>();
    xupd_kernel<<<4, 256>>>(xres, mask, gamma, out + OUT_X);

    // 7. output projection + residual
    tgemm_kernel<64, 64><<<dim3(8, 16), 256>>>(OFF_ATTN, wo, wo, wo, wo, DD,
                                               OFF_HMID, 0, h, -1, mask, NN, DD);

    // 8. FFN
    ln_kernel<<<NN, 256>>>(0, OFF_HMID, lnfw, lnfb, OFF_H2);
    tgemm_kernel<128, 128><<<dim3(32, 8), 256>>>(OFF_H2, w1, w3, w1, w1, 4 * DD,
                                                 OFF_FFA, 0, 0, -1, 0, NN, DD);
    silu_kernel<<<(NN * 4 * DD + 255) / 256, 256>>>();
    tgemm_kernel<64, 64><<<dim3(8, 16), 256>>>(OFF_FFG, w2, w2, w2, w2, DD,
                                               0, out + OUT_H, 0, OFF_HMID, mask, NN, 4 * DD);
}